// round 3
// baseline (speedup 1.0000x reference)
#include <cuda_runtime.h>
#include <cuda_bf16.h>
#include <math.h>

// Problem constants
#define NN   16384
#define EE   8192
#define DIM  256
#define CAP_R 128
#define CAP_C 192
#define LN_EPS 1e-5f

// ---------------- static device scratch (no allocations allowed) ------------
__device__ int   g_cols[NN * CAP_R];
__device__ int   g_rows[EE * CAP_C];
__device__ int   g_rcnt[NN];
__device__ int   g_ccnt[EE];
__device__ float g_invsv[NN];
__device__ float g_invse[EE];

__device__ float g_tmpE[EE * DIM];
__device__ float g_x1a [EE * DIM];
__device__ float g_msg [NN * DIM];
__device__ float g_u   [NN * DIM];
__device__ float g_x0l [NN * DIM];
__device__ float g_x0g [NN * DIM];
__device__ float g_ret [EE * DIM];
__device__ float g_h   [NN * 2 * DIM];

// ---------------- sparse build ----------------------------------------------
__global__ void zero_ccnt_kernel() {
    int j = blockIdx.x * blockDim.x + threadIdx.x;
    if (j < EE) g_ccnt[j] = 0;
}

__global__ __launch_bounds__(256) void build_csr_kernel(const float* __restrict__ H) {
    int warp = (blockIdx.x * blockDim.x + threadIdx.x) >> 5;
    int lane = threadIdx.x & 31;
    if (warp >= NN) return;
    const float* row = H + (size_t)warp * EE;
    int base = 0;
    for (int it = 0; it < EE / 128; it++) {
        float4 v4 = *(const float4*)(row + it * 128 + lane * 4);
        float v[4] = {v4.x, v4.y, v4.z, v4.w};
#pragma unroll
        for (int j = 0; j < 4; j++) {
            unsigned m = __ballot_sync(0xffffffffu, v[j] != 0.0f);
            if (v[j] != 0.0f) {
                int pos = base + __popc(m & ((1u << lane) - 1u));
                if (pos < CAP_R) g_cols[warp * CAP_R + pos] = it * 128 + lane * 4 + j;
            }
            base += __popc(m);
        }
    }
    if (lane == 0) {
        g_rcnt[warp]  = min(base, CAP_R);
        g_invsv[warp] = rsqrtf(fmaxf((float)base, 1.0f));
    }
}

__global__ void scatter_csc_kernel() {
    int tid = blockIdx.x * blockDim.x + threadIdx.x;
    int row = tid >> 7;
    int k   = tid & (CAP_R - 1);
    if (row >= NN) return;
    if (k < g_rcnt[row]) {
        int col = g_cols[row * CAP_R + k];
        int p = atomicAdd(&g_ccnt[col], 1);
        if (p < CAP_C) g_rows[col * CAP_C + p] = row;
    }
}

__global__ void finalize_cols_kernel() {
    int j = blockIdx.x * blockDim.x + threadIdx.x;
    if (j < EE) {
        int c = g_ccnt[j];
        g_invse[j] = rsqrtf(fmaxf((float)c, 1.0f));
        g_ccnt[j]  = min(c, CAP_C);
    }
}

// ---------------- SpMM gathers ----------------------------------------------
__global__ __launch_bounds__(DIM) void spmm_edges_kernel(const float* __restrict__ src,
                                                         float* __restrict__ out) {
    int e = blockIdx.x;
    int t = threadIdx.x;
    int cnt = g_ccnt[e];
    const int* lst = &g_rows[e * CAP_C];
    float a0 = 0.f, a1 = 0.f, a2 = 0.f, a3 = 0.f;
    int k = 0;
    for (; k + 4 <= cnt; k += 4) {
        int i0 = lst[k], i1 = lst[k+1], i2 = lst[k+2], i3 = lst[k+3];
        a0 = fmaf(src[(size_t)i0 * DIM + t], g_invsv[i0], a0);
        a1 = fmaf(src[(size_t)i1 * DIM + t], g_invsv[i1], a1);
        a2 = fmaf(src[(size_t)i2 * DIM + t], g_invsv[i2], a2);
        a3 = fmaf(src[(size_t)i3 * DIM + t], g_invsv[i3], a3);
    }
    for (; k < cnt; k++) {
        int i0 = lst[k];
        a0 = fmaf(src[(size_t)i0 * DIM + t], g_invsv[i0], a0);
    }
    out[(size_t)e * DIM + t] = ((a0 + a1) + (a2 + a3)) * g_invse[e];
}

__global__ __launch_bounds__(DIM) void spmm_nodes_kernel(const float* __restrict__ src,
                                                         float* __restrict__ out) {
    int i = blockIdx.x;
    int t = threadIdx.x;
    int cnt = g_rcnt[i];
    const int* lst = &g_cols[i * CAP_R];
    float a0 = 0.f, a1 = 0.f, a2 = 0.f, a3 = 0.f;
    int k = 0;
    for (; k + 4 <= cnt; k += 4) {
        int e0 = lst[k], e1 = lst[k+1], e2 = lst[k+2], e3 = lst[k+3];
        a0 = fmaf(src[(size_t)e0 * DIM + t], g_invse[e0], a0);
        a1 = fmaf(src[(size_t)e1 * DIM + t], g_invse[e1], a1);
        a2 = fmaf(src[(size_t)e2 * DIM + t], g_invse[e2], a2);
        a3 = fmaf(src[(size_t)e3 * DIM + t], g_invse[e3], a3);
    }
    for (; k < cnt; k++) {
        int e0 = lst[k];
        a0 = fmaf(src[(size_t)e0 * DIM + t], g_invse[e0], a0);
    }
    out[(size_t)i * DIM + t] = ((a0 + a1) + (a2 + a3)) * g_invsv[i];
}

// ---------------- tensor-core GEMM: bf16x3 (hi/lo split), fp32 accumulate ---
// C[M,N] = epi( A[M,K] @ B[K,N] )
// CTA tile 128x128, 8 warps of 64x32, KTILE=32 (two m16n8k16 k-steps).
__device__ __forceinline__ void mma_bf16(float* c, const unsigned* a, const unsigned* b) {
    asm volatile(
        "mma.sync.aligned.m16n8k16.row.col.f32.bf16.bf16.f32 "
        "{%0,%1,%2,%3}, {%4,%5,%6,%7}, {%8,%9}, {%0,%1,%2,%3};\n"
        : "+f"(c[0]), "+f"(c[1]), "+f"(c[2]), "+f"(c[3])
        : "r"(a[0]), "r"(a[1]), "r"(a[2]), "r"(a[3]), "r"(b[0]), "r"(b[1]));
}

template<bool RESID, bool GELU>
__global__ __launch_bounds__(256) void gemm_tc_kernel(
    const float* __restrict__ A, const float* __restrict__ B,
    const float* __restrict__ bias, const float* __restrict__ resid,
    const float* __restrict__ gate, float* __restrict__ C,
    int M, int N, int K)
{
    // pitch 20 u32 per row => conflict-free fragment loads (banks 20g+c all distinct)
    __shared__ unsigned Ah[128][20];
    __shared__ unsigned Al[128][20];
    __shared__ unsigned Bh[128][20];   // [n][k-pairs], B col-major for mma (k contiguous)
    __shared__ unsigned Bl[128][20];

    const int tid  = threadIdx.x;
    const int warp = tid >> 5;
    const int lane = tid & 31;
    const int grp  = lane >> 2;      // 0..7
    const int qd   = lane & 3;       // 0..3
    const int m0 = blockIdx.y * 128;
    const int n0 = blockIdx.x * 128;
    const int warpM = (warp >> 2) * 64;   // 2 warp rows
    const int warpN = (warp & 3) * 32;    // 4 warp cols

    float acc[2][4][4][4];   // [mhalf? no] -> [mf up to 4][nf 4][4]
    // 64/16 = 4 mfrags, 32/8 = 4 nfrags
#pragma unroll
    for (int mf = 0; mf < 4; mf++)
#pragma unroll
        for (int nf = 0; nf < 4; nf++)
#pragma unroll
            for (int r = 0; r < 4; r++) acc[0][mf][nf][r] = 0.0f;

    // gmem prefetch registers (tile t+1 loaded during compute of tile t)
    float4 ra[4], rb[4];

    const int a_m  = tid >> 3;              // 0..31 -> but need 128 rows / (256/8=32 rows per pass) x4
    const int a_k4 = (tid & 7) * 4;
    const int b_k  = tid >> 5;              // 0..7
    const int b_n4 = (tid & 31) * 4;

    // load tile 0
#pragma unroll
    for (int i = 0; i < 4; i++)
        ra[i] = *(const float4*)(A + (size_t)(m0 + a_m + i * 32) * K + a_k4);
#pragma unroll
    for (int i = 0; i < 4; i++)
        rb[i] = *(const float4*)(B + (size_t)(b_k + i * 8) * N + n0 + b_n4);

    const int ntiles = K / 32;
    for (int t = 0; t < ntiles; t++) {
        // convert + store to smem
        __nv_bfloat16* bh16 = (__nv_bfloat16*)&Bh[0][0];   // pitch 40 bf16
        __nv_bfloat16* bl16 = (__nv_bfloat16*)&Bl[0][0];
#pragma unroll
        for (int i = 0; i < 4; i++) {
            float4 v = ra[i];
            __nv_bfloat162 h01 = __floats2bfloat162_rn(v.x, v.y);
            __nv_bfloat162 h23 = __floats2bfloat162_rn(v.z, v.w);
            float2 f01 = __bfloat1622float2(h01);
            float2 f23 = __bfloat1622float2(h23);
            __nv_bfloat162 l01 = __floats2bfloat162_rn(v.x - f01.x, v.y - f01.y);
            __nv_bfloat162 l23 = __floats2bfloat162_rn(v.z - f23.x, v.w - f23.y);
            int m = a_m + i * 32;
            Ah[m][a_k4 / 2]     = *(unsigned*)&h01;
            Ah[m][a_k4 / 2 + 1] = *(unsigned*)&h23;
            Al[m][a_k4 / 2]     = *(unsigned*)&l01;
            Al[m][a_k4 / 2 + 1] = *(unsigned*)&l23;
        }
#pragma unroll
        for (int i = 0; i < 4; i++) {
            float4 v = rb[i];
            int kk = b_k + i * 8;
            float vv[4] = {v.x, v.y, v.z, v.w};
#pragma unroll
            for (int j = 0; j < 4; j++) {
                __nv_bfloat16 h = __float2bfloat16_rn(vv[j]);
                __nv_bfloat16 l = __float2bfloat16_rn(vv[j] - __bfloat162float(h));
                bh16[(b_n4 + j) * 40 + kk] = h;
                bl16[(b_n4 + j) * 40 + kk] = l;
            }
        }
        __syncthreads();

        // prefetch next tile
        if (t + 1 < ntiles) {
            int k0 = (t + 1) * 32;
#pragma unroll
            for (int i = 0; i < 4; i++)
                ra[i] = *(const float4*)(A + (size_t)(m0 + a_m + i * 32) * K + k0 + a_k4);
#pragma unroll
            for (int i = 0; i < 4; i++)
                rb[i] = *(const float4*)(B + (size_t)(k0 + b_k + i * 8) * N + n0 + b_n4);
        }

        // compute: two k-steps of 16
#pragma unroll
        for (int ks = 0; ks < 2; ks++) {
            const int kb = ks * 8;  // u32 (k-pair) base
            unsigned afh[4][4], afl[4][4], bf[4][2];
#pragma unroll
            for (int mf = 0; mf < 4; mf++) {
                int mrow = warpM + mf * 16 + grp;
                afh[mf][0] = Ah[mrow][kb + qd];
                afh[mf][1] = Ah[mrow + 8][kb + qd];
                afh[mf][2] = Ah[mrow][kb + qd + 4];
                afh[mf][3] = Ah[mrow + 8][kb + qd + 4];
                afl[mf][0] = Al[mrow][kb + qd];
                afl[mf][1] = Al[mrow + 8][kb + qd];
                afl[mf][2] = Al[mrow][kb + qd + 4];
                afl[mf][3] = Al[mrow + 8][kb + qd + 4];
            }
#pragma unroll
            for (int nf = 0; nf < 4; nf++) {
                int nrow = warpN + nf * 8 + grp;
                bf[nf][0] = Bh[nrow][kb + qd];
                bf[nf][1] = Bh[nrow][kb + qd + 4];
            }
            // hi*hi and lo*hi
#pragma unroll
            for (int mf = 0; mf < 4; mf++)
#pragma unroll
                for (int nf = 0; nf < 4; nf++) {
                    mma_bf16(acc[0][mf][nf], afh[mf], bf[nf]);
                    mma_bf16(acc[0][mf][nf], afl[mf], bf[nf]);
                }
            // hi*lo
#pragma unroll
            for (int nf = 0; nf < 4; nf++) {
                int nrow = warpN + nf * 8 + grp;
                bf[nf][0] = Bl[nrow][kb + qd];
                bf[nf][1] = Bl[nrow][kb + qd + 4];
            }
#pragma unroll
            for (int mf = 0; mf < 4; mf++)
#pragma unroll
                for (int nf = 0; nf < 4; nf++)
                    mma_bf16(acc[0][mf][nf], afh[mf], bf[nf]);
        }
        __syncthreads();
    }

    // epilogue
    float alpha = 1.0f;
    if (!GELU && gate != nullptr) alpha = tanhf(gate[0]);

#pragma unroll
    for (int mf = 0; mf < 4; mf++) {
#pragma unroll
        for (int nf = 0; nf < 4; nf++) {
            int col = n0 + warpN + nf * 8 + 2 * qd;
            float bv0 = bias[col], bv1 = bias[col + 1];
            int r0 = m0 + warpM + mf * 16 + grp;
#pragma unroll
            for (int half = 0; half < 2; half++) {
                int row = r0 + half * 8;
                float v0 = acc[0][mf][nf][half * 2 + 0] + bv0;
                float v1 = acc[0][mf][nf][half * 2 + 1] + bv1;
                if (GELU) {
                    v0 = 0.5f * v0 * (1.0f + erff(v0 * 0.7071067811865476f));
                    v1 = 0.5f * v1 * (1.0f + erff(v1 * 0.7071067811865476f));
                } else {
                    v0 *= alpha; v1 *= alpha;
                }
                size_t base = (size_t)row * N + col;
                if (RESID) {
                    float2 r = *(const float2*)(resid + base);
                    v0 += r.x; v1 += r.y;
                }
                float2 o = make_float2(v0, v1);
                *(float2*)(C + base) = o;
            }
        }
    }
}

// ---------------- fused double LayerNorm -------------------------------------
__device__ __forceinline__ float block_sum_256(float v, float* sm) {
#pragma unroll
    for (int o = 16; o > 0; o >>= 1) v += __shfl_xor_sync(0xffffffffu, v, o);
    int w = threadIdx.x >> 5, lane = threadIdx.x & 31;
    if (lane == 0) sm[w] = v;
    __syncthreads();
    if (w == 0) {
        float s = (lane < 8) ? sm[lane] : 0.0f;
#pragma unroll
        for (int o = 4; o > 0; o >>= 1) s += __shfl_xor_sync(0xffffffffu, s, o);
        if (lane == 0) sm[0] = s;
    }
    __syncthreads();
    float r = sm[0];
    __syncthreads();
    return r;
}

__global__ __launch_bounds__(DIM) void ln_double_kernel(
    const float* __restrict__ g1, const float* __restrict__ b1,
    const float* __restrict__ g2, const float* __restrict__ b2)
{
    __shared__ float sm[8];
    int r = blockIdx.x, t = threadIdx.x;
    float v = g_u[(size_t)r * DIM + t];
    float mean = block_sum_256(v, sm) * (1.0f / DIM);
    float d = v - mean;
    float var = block_sum_256(d * d, sm) * (1.0f / DIM);
    float y = d * rsqrtf(var + LN_EPS) * g1[t] + b1[t];
    g_x0l[(size_t)r * DIM + t] = y;
    float m2 = block_sum_256(y, sm) * (1.0f / DIM);
    float d2 = y - m2;
    float v2 = block_sum_256(d2 * d2, sm) * (1.0f / DIM);
    g_x0g[(size_t)r * DIM + t] = d2 * rsqrtf(v2 + LN_EPS) * g2[t] + b2[t];
}

// ---------------- driver -----------------------------------------------------
extern "C" void kernel_launch(void* const* d_in, const int* in_sizes, int n_in,
                              void* d_out, int out_size) {
    const float* x0   = (const float*)d_in[0];
    const float* x1   = (const float*)d_in[1];
    const float* H    = (const float*)d_in[2];
    const float* Wn   = (const float*)d_in[3];
    const float* bn   = (const float*)d_in[4];
    const float* We   = (const float*)d_in[5];
    const float* be   = (const float*)d_in[6];
    const float* Wr   = (const float*)d_in[7];
    const float* br   = (const float*)d_in[8];
    const float* W1   = (const float*)d_in[9];
    const float* b1   = (const float*)d_in[10];
    const float* W2   = (const float*)d_in[11];
    const float* b2   = (const float*)d_in[12];
    const float* ln1g = (const float*)d_in[13];
    const float* ln1b = (const float*)d_in[14];
    const float* ln2g = (const float*)d_in[15];
    const float* ln2b = (const float*)d_in[16];
    const float* gl   = (const float*)d_in[17];
    const float* gr   = (const float*)d_in[18];

    float* out_x0 = (float*)d_out;
    float* out_x1 = (float*)d_out + (size_t)NN * DIM;

    float *p_tmpE, *p_x1a, *p_msg, *p_u, *p_x0l, *p_x0g, *p_ret, *p_h;
    cudaGetSymbolAddress((void**)&p_tmpE, g_tmpE);
    cudaGetSymbolAddress((void**)&p_x1a,  g_x1a);
    cudaGetSymbolAddress((void**)&p_msg,  g_msg);
    cudaGetSymbolAddress((void**)&p_u,    g_u);
    cudaGetSymbolAddress((void**)&p_x0l,  g_x0l);
    cudaGetSymbolAddress((void**)&p_x0g,  g_x0g);
    cudaGetSymbolAddress((void**)&p_ret,  g_ret);
    cudaGetSymbolAddress((void**)&p_h,    g_h);

    // 1) sparse structure build
    zero_ccnt_kernel<<<EE / 256, 256>>>();
    build_csr_kernel<<<NN / 8, 256>>>(H);
    scatter_csc_kernel<<<(NN * CAP_R) / 256, 256>>>();
    finalize_cols_kernel<<<EE / 256, 256>>>();

    // 2) tmpE = H_norm^T @ x0
    spmm_edges_kernel<<<EE, DIM>>>(x0, p_tmpE);
    // 3) x1a = x1 + tmpE @ We + be
    gemm_tc_kernel<true, false><<<dim3(DIM / 128, EE / 128), 256>>>(
        p_tmpE, We, be, x1, nullptr, p_x1a, EE, DIM, DIM);
    // 4) msg = H_norm @ x1a
    spmm_nodes_kernel<<<NN, DIM>>>(p_x1a, p_msg);
    // 5) u = x0 + tanh(gl) * (msg @ Wn + bn)
    gemm_tc_kernel<true, false><<<dim3(DIM / 128, NN / 128), 256>>>(
        p_msg, Wn, bn, x0, gl, p_u, NN, DIM, DIM);
    // 6) LN1 + LN2
    ln_double_kernel<<<NN, DIM>>>(ln1g, ln1b, ln2g, ln2b);
    // 7) ret = H_norm^T @ x0_local
    spmm_edges_kernel<<<EE, DIM>>>(p_x0l, p_ret);
    // 8) x1_out = x1a + tanh(gr) * (ret @ Wr + br)
    gemm_tc_kernel<true, false><<<dim3(DIM / 128, EE / 128), 256>>>(
        p_ret, Wr, br, p_x1a, gr, out_x1, EE, DIM, DIM);
    // 9) h = gelu(x0_global @ W1 + b1)
    gemm_tc_kernel<false, true><<<dim3((2 * DIM) / 128, NN / 128), 256>>>(
        p_x0g, W1, b1, nullptr, nullptr, p_h, NN, 2 * DIM, DIM);
    // 10) x0_out = x0_global + h @ W2 + b2
    gemm_tc_kernel<true, false><<<dim3(DIM / 128, NN / 128), 256>>>(
        p_h, W2, b2, p_x0g, nullptr, out_x0, NN, DIM, 2 * DIM);

    (void)in_sizes; (void)n_in; (void)out_size;
}

// round 4
// speedup vs baseline: 1.0905x; 1.0905x over previous
#include <cuda_runtime.h>
#include <cuda_bf16.h>
#include <math.h>

// Problem constants
#define NN   16384
#define EE   8192
#define DIM  256
#define CAP_R 128
#define CAP_C 192
#define LN_EPS 1e-5f

// ---------------- static device scratch (no allocations allowed) ------------
__device__ int   g_cols[NN * CAP_R];
__device__ int   g_rows[EE * CAP_C];
__device__ int   g_rcnt[NN];
__device__ int   g_ccnt[EE];
__device__ float g_invsv[NN];
__device__ float g_invse[EE];

__device__ float g_tmpE[EE * DIM];
__device__ float g_x1a [EE * DIM];
__device__ float g_msg [NN * DIM];
__device__ float g_u   [NN * DIM];
__device__ float g_x0g [NN * DIM];
__device__ float g_ret [EE * DIM];
__device__ float g_h   [NN * 2 * DIM];

// bf16 gather sources for the SpMMs
__device__ __nv_bfloat162 g_x0bf [NN * DIM / 2];
__device__ __nv_bfloat162 g_x1abf[EE * DIM / 2];
__device__ __nv_bfloat162 g_x0lbf[NN * DIM / 2];

// ---------------- sparse build ----------------------------------------------
// Fused: also zeroes g_ccnt (consumed only by the later scatter kernel).
__global__ __launch_bounds__(256) void build_csr_kernel(const float* __restrict__ H) {
    int gtid = blockIdx.x * blockDim.x + threadIdx.x;
    if (gtid < EE) g_ccnt[gtid] = 0;

    int warp = gtid >> 5;
    int lane = threadIdx.x & 31;
    if (warp >= NN) return;
    const float* row = H + (size_t)warp * EE;
    int base = 0;
    for (int it = 0; it < EE / 128; it++) {
        float4 v4 = *(const float4*)(row + it * 128 + lane * 4);
        float v[4] = {v4.x, v4.y, v4.z, v4.w};
#pragma unroll
        for (int j = 0; j < 4; j++) {
            unsigned m = __ballot_sync(0xffffffffu, v[j] != 0.0f);
            if (v[j] != 0.0f) {
                int pos = base + __popc(m & ((1u << lane) - 1u));
                if (pos < CAP_R) g_cols[warp * CAP_R + pos] = it * 128 + lane * 4 + j;
            }
            base += __popc(m);
        }
    }
    if (lane == 0) {
        g_rcnt[warp]  = min(base, CAP_R);
        g_invsv[warp] = rsqrtf(fmaxf((float)base, 1.0f));
    }
}

// Fused: CSR->CSC scatter + x0 -> bf16 conversion (each thread converts one pair).
__global__ void scatter_cvt_kernel(const float* __restrict__ x0) {
    int tid = blockIdx.x * blockDim.x + threadIdx.x;   // 0 .. NN*CAP_R-1 (= 2*NN*DIM/4... )
    // x0 conversion: NN*DIM/2 = 2,097,152 pairs == NN*CAP_R threads exactly
    float2 p = *(const float2*)(x0 + (size_t)tid * 2);
    g_x0bf[tid] = __floats2bfloat162_rn(p.x, p.y);

    int row = tid >> 7;               // / CAP_R
    int k   = tid & (CAP_R - 1);
    if (k < g_rcnt[row]) {
        int col = g_cols[row * CAP_R + k];
        int p2 = atomicAdd(&g_ccnt[col], 1);
        if (p2 < CAP_C) g_rows[col * CAP_C + p2] = row;
    }
}

__global__ void finalize_cols_kernel() {
    int j = blockIdx.x * blockDim.x + threadIdx.x;
    if (j < EE) {
        int c = g_ccnt[j];
        g_invse[j] = rsqrtf(fmaxf((float)c, 1.0f));
        g_ccnt[j]  = min(c, CAP_C);
    }
}

// ---------------- SpMM gathers (bf16 sources, fp32 accumulate) ---------------
// out[e,:] = invse[e] * sum_{i in edge e} invsv[i] * src[i,:]
__global__ __launch_bounds__(128) void spmm_edges_kernel(const __nv_bfloat162* __restrict__ src,
                                                         float* __restrict__ out) {
    int e = blockIdx.x;
    int t = threadIdx.x;                 // handles dims 2t, 2t+1
    int cnt = g_ccnt[e];
    const int* lst = &g_rows[e * CAP_C];
    float2 a0 = {0.f,0.f}, a1 = {0.f,0.f}, a2 = {0.f,0.f}, a3 = {0.f,0.f};
    int k = 0;
    for (; k + 4 <= cnt; k += 4) {
        int i0 = lst[k], i1 = lst[k+1], i2 = lst[k+2], i3 = lst[k+3];
        float2 f0 = __bfloat1622float2(src[(size_t)i0 * 128 + t]);
        float2 f1 = __bfloat1622float2(src[(size_t)i1 * 128 + t]);
        float2 f2 = __bfloat1622float2(src[(size_t)i2 * 128 + t]);
        float2 f3 = __bfloat1622float2(src[(size_t)i3 * 128 + t]);
        float s0 = g_invsv[i0], s1 = g_invsv[i1], s2 = g_invsv[i2], s3 = g_invsv[i3];
        a0.x = fmaf(f0.x, s0, a0.x); a0.y = fmaf(f0.y, s0, a0.y);
        a1.x = fmaf(f1.x, s1, a1.x); a1.y = fmaf(f1.y, s1, a1.y);
        a2.x = fmaf(f2.x, s2, a2.x); a2.y = fmaf(f2.y, s2, a2.y);
        a3.x = fmaf(f3.x, s3, a3.x); a3.y = fmaf(f3.y, s3, a3.y);
    }
    for (; k < cnt; k++) {
        int i0 = lst[k];
        float2 f0 = __bfloat1622float2(src[(size_t)i0 * 128 + t]);
        float s0 = g_invsv[i0];
        a0.x = fmaf(f0.x, s0, a0.x); a0.y = fmaf(f0.y, s0, a0.y);
    }
    float se = g_invse[e];
    float2 o = make_float2(((a0.x + a1.x) + (a2.x + a3.x)) * se,
                           ((a0.y + a1.y) + (a2.y + a3.y)) * se);
    *(float2*)(out + (size_t)e * DIM + t * 2) = o;
}

// out[i,:] = invsv[i] * sum_{e in node i} invse[e] * src[e,:]
__global__ __launch_bounds__(128) void spmm_nodes_kernel(const __nv_bfloat162* __restrict__ src,
                                                         float* __restrict__ out) {
    int i = blockIdx.x;
    int t = threadIdx.x;
    int cnt = g_rcnt[i];
    const int* lst = &g_cols[i * CAP_R];
    float2 a0 = {0.f,0.f}, a1 = {0.f,0.f}, a2 = {0.f,0.f}, a3 = {0.f,0.f};
    int k = 0;
    for (; k + 4 <= cnt; k += 4) {
        int e0 = lst[k], e1 = lst[k+1], e2 = lst[k+2], e3 = lst[k+3];
        float2 f0 = __bfloat1622float2(src[(size_t)e0 * 128 + t]);
        float2 f1 = __bfloat1622float2(src[(size_t)e1 * 128 + t]);
        float2 f2 = __bfloat1622float2(src[(size_t)e2 * 128 + t]);
        float2 f3 = __bfloat1622float2(src[(size_t)e3 * 128 + t]);
        float s0 = g_invse[e0], s1 = g_invse[e1], s2 = g_invse[e2], s3 = g_invse[e3];
        a0.x = fmaf(f0.x, s0, a0.x); a0.y = fmaf(f0.y, s0, a0.y);
        a1.x = fmaf(f1.x, s1, a1.x); a1.y = fmaf(f1.y, s1, a1.y);
        a2.x = fmaf(f2.x, s2, a2.x); a2.y = fmaf(f2.y, s2, a2.y);
        a3.x = fmaf(f3.x, s3, a3.x); a3.y = fmaf(f3.y, s3, a3.y);
    }
    for (; k < cnt; k++) {
        int e0 = lst[k];
        float2 f0 = __bfloat1622float2(src[(size_t)e0 * 128 + t]);
        float s0 = g_invse[e0];
        a0.x = fmaf(f0.x, s0, a0.x); a0.y = fmaf(f0.y, s0, a0.y);
    }
    float sv = g_invsv[i];
    float2 o = make_float2(((a0.x + a1.x) + (a2.x + a3.x)) * sv,
                           ((a0.y + a1.y) + (a2.y + a3.y)) * sv);
    *(float2*)(out + (size_t)i * DIM + t * 2) = o;
}

// ---------------- tensor-core GEMM: bf16x3 (hi/lo split), fp32 accumulate ---
__device__ __forceinline__ void mma_bf16(float* c, const unsigned* a, const unsigned* b) {
    asm volatile(
        "mma.sync.aligned.m16n8k16.row.col.f32.bf16.bf16.f32 "
        "{%0,%1,%2,%3}, {%4,%5,%6,%7}, {%8,%9}, {%0,%1,%2,%3};\n"
        : "+f"(c[0]), "+f"(c[1]), "+f"(c[2]), "+f"(c[3])
        : "r"(a[0]), "r"(a[1]), "r"(a[2]), "r"(a[3]), "r"(b[0]), "r"(b[1]));
}

template<bool RESID, bool GELU>
__global__ __launch_bounds__(256) void gemm_tc_kernel(
    const float* __restrict__ A, const float* __restrict__ B,
    const float* __restrict__ bias, const float* __restrict__ resid,
    const float* __restrict__ gate, float* __restrict__ C,
    __nv_bfloat162* __restrict__ bfc,   // optional bf16 copy of C
    int M, int N, int K)
{
    __shared__ unsigned Ah[128][20];
    __shared__ unsigned Al[128][20];
    __shared__ unsigned Bh[128][20];
    __shared__ unsigned Bl[128][20];

    const int tid  = threadIdx.x;
    const int warp = tid >> 5;
    const int lane = tid & 31;
    const int grp  = lane >> 2;
    const int qd   = lane & 3;
    const int m0 = blockIdx.y * 128;
    const int n0 = blockIdx.x * 128;
    const int warpM = (warp >> 2) * 64;
    const int warpN = (warp & 3) * 32;

    float acc[4][4][4];
#pragma unroll
    for (int mf = 0; mf < 4; mf++)
#pragma unroll
        for (int nf = 0; nf < 4; nf++)
#pragma unroll
            for (int r = 0; r < 4; r++) acc[mf][nf][r] = 0.0f;

    float4 ra[4], rb[4];
    const int a_m  = tid >> 3;
    const int a_k4 = (tid & 7) * 4;
    const int b_k  = tid >> 5;
    const int b_n4 = (tid & 31) * 4;

#pragma unroll
    for (int i = 0; i < 4; i++)
        ra[i] = *(const float4*)(A + (size_t)(m0 + a_m + i * 32) * K + a_k4);
#pragma unroll
    for (int i = 0; i < 4; i++)
        rb[i] = *(const float4*)(B + (size_t)(b_k + i * 8) * N + n0 + b_n4);

    const int ntiles = K / 32;
    for (int t = 0; t < ntiles; t++) {
        __nv_bfloat16* bh16 = (__nv_bfloat16*)&Bh[0][0];
        __nv_bfloat16* bl16 = (__nv_bfloat16*)&Bl[0][0];
#pragma unroll
        for (int i = 0; i < 4; i++) {
            float4 v = ra[i];
            __nv_bfloat162 h01 = __floats2bfloat162_rn(v.x, v.y);
            __nv_bfloat162 h23 = __floats2bfloat162_rn(v.z, v.w);
            float2 f01 = __bfloat1622float2(h01);
            float2 f23 = __bfloat1622float2(h23);
            __nv_bfloat162 l01 = __floats2bfloat162_rn(v.x - f01.x, v.y - f01.y);
            __nv_bfloat162 l23 = __floats2bfloat162_rn(v.z - f23.x, v.w - f23.y);
            int m = a_m + i * 32;
            Ah[m][a_k4 / 2]     = *(unsigned*)&h01;
            Ah[m][a_k4 / 2 + 1] = *(unsigned*)&h23;
            Al[m][a_k4 / 2]     = *(unsigned*)&l01;
            Al[m][a_k4 / 2 + 1] = *(unsigned*)&l23;
        }
#pragma unroll
        for (int i = 0; i < 4; i++) {
            float4 v = rb[i];
            int kk = b_k + i * 8;
            float vv[4] = {v.x, v.y, v.z, v.w};
#pragma unroll
            for (int j = 0; j < 4; j++) {
                __nv_bfloat16 h = __float2bfloat16_rn(vv[j]);
                __nv_bfloat16 l = __float2bfloat16_rn(vv[j] - __bfloat162float(h));
                bh16[(b_n4 + j) * 40 + kk] = h;
                bl16[(b_n4 + j) * 40 + kk] = l;
            }
        }
        __syncthreads();

        if (t + 1 < ntiles) {
            int k0 = (t + 1) * 32;
#pragma unroll
            for (int i = 0; i < 4; i++)
                ra[i] = *(const float4*)(A + (size_t)(m0 + a_m + i * 32) * K + k0 + a_k4);
#pragma unroll
            for (int i = 0; i < 4; i++)
                rb[i] = *(const float4*)(B + (size_t)(k0 + b_k + i * 8) * N + n0 + b_n4);
        }

#pragma unroll
        for (int ks = 0; ks < 2; ks++) {
            const int kb = ks * 8;
            unsigned afh[4][4], afl[4][4], bf[4][2];
#pragma unroll
            for (int mf = 0; mf < 4; mf++) {
                int mrow = warpM + mf * 16 + grp;
                afh[mf][0] = Ah[mrow][kb + qd];
                afh[mf][1] = Ah[mrow + 8][kb + qd];
                afh[mf][2] = Ah[mrow][kb + qd + 4];
                afh[mf][3] = Ah[mrow + 8][kb + qd + 4];
                afl[mf][0] = Al[mrow][kb + qd];
                afl[mf][1] = Al[mrow + 8][kb + qd];
                afl[mf][2] = Al[mrow][kb + qd + 4];
                afl[mf][3] = Al[mrow + 8][kb + qd + 4];
            }
#pragma unroll
            for (int nf = 0; nf < 4; nf++) {
                int nrow = warpN + nf * 8 + grp;
                bf[nf][0] = Bh[nrow][kb + qd];
                bf[nf][1] = Bh[nrow][kb + qd + 4];
            }
#pragma unroll
            for (int mf = 0; mf < 4; mf++)
#pragma unroll
                for (int nf = 0; nf < 4; nf++) {
                    mma_bf16(acc[mf][nf], afh[mf], bf[nf]);
                    mma_bf16(acc[mf][nf], afl[mf], bf[nf]);
                }
#pragma unroll
            for (int nf = 0; nf < 4; nf++) {
                int nrow = warpN + nf * 8 + grp;
                bf[nf][0] = Bl[nrow][kb + qd];
                bf[nf][1] = Bl[nrow][kb + qd + 4];
            }
#pragma unroll
            for (int mf = 0; mf < 4; mf++)
#pragma unroll
                for (int nf = 0; nf < 4; nf++)
                    mma_bf16(acc[mf][nf], afh[mf], bf[nf]);
        }
        __syncthreads();
    }

    float alpha = 1.0f;
    if (!GELU && gate != nullptr) alpha = tanhf(gate[0]);

#pragma unroll
    for (int mf = 0; mf < 4; mf++) {
#pragma unroll
        for (int nf = 0; nf < 4; nf++) {
            int col = n0 + warpN + nf * 8 + 2 * qd;
            float bv0 = bias[col], bv1 = bias[col + 1];
            int r0 = m0 + warpM + mf * 16 + grp;
#pragma unroll
            for (int half = 0; half < 2; half++) {
                int row = r0 + half * 8;
                float v0 = acc[mf][nf][half * 2 + 0] + bv0;
                float v1 = acc[mf][nf][half * 2 + 1] + bv1;
                if (GELU) {
                    v0 = 0.5f * v0 * (1.0f + erff(v0 * 0.7071067811865476f));
                    v1 = 0.5f * v1 * (1.0f + erff(v1 * 0.7071067811865476f));
                } else {
                    v0 *= alpha; v1 *= alpha;
                }
                size_t base = (size_t)row * N + col;
                if (RESID) {
                    float2 r = *(const float2*)(resid + base);
                    v0 += r.x; v1 += r.y;
                }
                *(float2*)(C + base) = make_float2(v0, v1);
                if (bfc) bfc[base >> 1] = __floats2bfloat162_rn(v0, v1);
            }
        }
    }
}

// ---------------- fused double LayerNorm -------------------------------------
__device__ __forceinline__ float block_sum_256(float v, float* sm) {
#pragma unroll
    for (int o = 16; o > 0; o >>= 1) v += __shfl_xor_sync(0xffffffffu, v, o);
    int w = threadIdx.x >> 5, lane = threadIdx.x & 31;
    if (lane == 0) sm[w] = v;
    __syncthreads();
    if (w == 0) {
        float s = (lane < 8) ? sm[lane] : 0.0f;
#pragma unroll
        for (int o = 4; o > 0; o >>= 1) s += __shfl_xor_sync(0xffffffffu, s, o);
        if (lane == 0) sm[0] = s;
    }
    __syncthreads();
    float r = sm[0];
    __syncthreads();
    return r;
}

// LN1 output only needed as bf16 (feeds the ret SpMM); LN2 output fp32.
__global__ __launch_bounds__(DIM) void ln_double_kernel(
    const float* __restrict__ g1, const float* __restrict__ b1,
    const float* __restrict__ g2, const float* __restrict__ b2)
{
    __shared__ float sm[8];
    int r = blockIdx.x, t = threadIdx.x;
    float v = g_u[(size_t)r * DIM + t];
    float mean = block_sum_256(v, sm) * (1.0f / DIM);
    float d = v - mean;
    float var = block_sum_256(d * d, sm) * (1.0f / DIM);
    float y = d * rsqrtf(var + LN_EPS) * g1[t] + b1[t];
    // bf16 copy of x0_local (pairs: even thread stores both lanes via shfl)
    {
        float y_hi = __shfl_xor_sync(0xffffffffu, y, 1);   // partner's value
        if ((t & 1) == 0)
            g_x0lbf[((size_t)r * DIM + t) >> 1] = __floats2bfloat162_rn(y, y_hi);
    }
    float m2 = block_sum_256(y, sm) * (1.0f / DIM);
    float d2 = y - m2;
    float v2 = block_sum_256(d2 * d2, sm) * (1.0f / DIM);
    g_x0g[(size_t)r * DIM + t] = d2 * rsqrtf(v2 + LN_EPS) * g2[t] + b2[t];
}

// ---------------- driver -----------------------------------------------------
extern "C" void kernel_launch(void* const* d_in, const int* in_sizes, int n_in,
                              void* d_out, int out_size) {
    const float* x0   = (const float*)d_in[0];
    const float* x1   = (const float*)d_in[1];
    const float* H    = (const float*)d_in[2];
    const float* Wn   = (const float*)d_in[3];
    const float* bn   = (const float*)d_in[4];
    const float* We   = (const float*)d_in[5];
    const float* be   = (const float*)d_in[6];
    const float* Wr   = (const float*)d_in[7];
    const float* br   = (const float*)d_in[8];
    const float* W1   = (const float*)d_in[9];
    const float* b1   = (const float*)d_in[10];
    const float* W2   = (const float*)d_in[11];
    const float* b2   = (const float*)d_in[12];
    const float* ln1g = (const float*)d_in[13];
    const float* ln1b = (const float*)d_in[14];
    const float* ln2g = (const float*)d_in[15];
    const float* ln2b = (const float*)d_in[16];
    const float* gl   = (const float*)d_in[17];
    const float* gr   = (const float*)d_in[18];

    float* out_x0 = (float*)d_out;
    float* out_x1 = (float*)d_out + (size_t)NN * DIM;

    float *p_tmpE, *p_x1a, *p_msg, *p_u, *p_x0g, *p_ret, *p_h;
    __nv_bfloat162 *p_x0bf, *p_x1abf, *p_x0lbf;
    cudaGetSymbolAddress((void**)&p_tmpE, g_tmpE);
    cudaGetSymbolAddress((void**)&p_x1a,  g_x1a);
    cudaGetSymbolAddress((void**)&p_msg,  g_msg);
    cudaGetSymbolAddress((void**)&p_u,    g_u);
    cudaGetSymbolAddress((void**)&p_x0g,  g_x0g);
    cudaGetSymbolAddress((void**)&p_ret,  g_ret);
    cudaGetSymbolAddress((void**)&p_h,    g_h);
    cudaGetSymbolAddress((void**)&p_x0bf,  g_x0bf);
    cudaGetSymbolAddress((void**)&p_x1abf, g_x1abf);
    cudaGetSymbolAddress((void**)&p_x0lbf, g_x0lbf);

    // 1) sparse build (ccnt zero fused) ; 2) scatter + x0->bf16 ; 3) finalize
    build_csr_kernel<<<NN / 8, 256>>>(H);
    scatter_cvt_kernel<<<(NN * CAP_R) / 256, 256>>>(x0);
    finalize_cols_kernel<<<EE / 256, 256>>>();

    // 4) tmpE = H_norm^T @ x0          <-- ncu's profiled slot
    spmm_edges_kernel<<<EE, 128>>>(p_x0bf, p_tmpE);
    // 5) x1a = x1 + tmpE @ We + be   (+ bf16 copy)
    gemm_tc_kernel<true, false><<<dim3(DIM / 128, EE / 128), 256>>>(
        p_tmpE, We, be, x1, nullptr, p_x1a, p_x1abf, EE, DIM, DIM);
    // 6) msg = H_norm @ x1a
    spmm_nodes_kernel<<<NN, 128>>>(p_x1abf, p_msg);
    // 7) u = x0 + tanh(gl) * (msg @ Wn + bn)
    gemm_tc_kernel<true, false><<<dim3(DIM / 128, NN / 128), 256>>>(
        p_msg, Wn, bn, x0, gl, p_u, nullptr, NN, DIM, DIM);
    // 8) LN1 (bf16 out) + LN2 (fp32 out)
    ln_double_kernel<<<NN, DIM>>>(ln1g, ln1b, ln2g, ln2b);
    // 9) ret = H_norm^T @ x0_local
    spmm_edges_kernel<<<EE, 128>>>(p_x0lbf, p_ret);
    // 10) x1_out = x1a + tanh(gr) * (ret @ Wr + br)
    gemm_tc_kernel<true, false><<<dim3(DIM / 128, EE / 128), 256>>>(
        p_ret, Wr, br, p_x1a, gr, out_x1, nullptr, EE, DIM, DIM);
    // 11) h = gelu(x0_global @ W1 + b1)
    gemm_tc_kernel<false, true><<<dim3((2 * DIM) / 128, NN / 128), 256>>>(
        p_x0g, W1, b1, nullptr, nullptr, p_h, nullptr, NN, 2 * DIM, DIM);
    // 12) x0_out = x0_global + h @ W2 + b2
    gemm_tc_kernel<true, false><<<dim3(DIM / 128, NN / 128), 256>>>(
        p_h, W2, b2, p_x0g, nullptr, out_x0, nullptr, NN, DIM, 2 * DIM);

    (void)in_sizes; (void)n_in; (void)out_size;
}

// round 5
// speedup vs baseline: 1.1067x; 1.0149x over previous
#include <cuda_runtime.h>
#include <cuda_bf16.h>
#include <math.h>

// Problem constants
#define NN   16384
#define EE   8192
#define DIM  256
#define CAP_R 128
#define CAP_C 192
#define LN_EPS 1e-5f

// Weight-plane offsets (elements) inside g_wh / g_wl
#define OFF_WE 0
#define OFF_WN 65536
#define OFF_WR 131072
#define OFF_W1 196608
#define OFF_W2 327680
#define W_TOTAL 458752

// ---------------- static device scratch (no allocations allowed) ------------
__device__ int   g_cols[NN * CAP_R];
__device__ int   g_rows[EE * CAP_C];
__device__ int   g_rcnt[NN];
__device__ int   g_ccnt[EE];
__device__ float g_invsv[NN];
__device__ float g_invse[EE];

__device__ float g_tmpE[EE * DIM];
__device__ float g_x1a [EE * DIM];
__device__ float g_msg [NN * DIM];
__device__ float g_u   [NN * DIM];
__device__ float g_x0g [NN * DIM];
__device__ float g_ret [EE * DIM];
__device__ float g_h   [NN * 2 * DIM];

// bf16 gather sources for the SpMMs (pre-scaled by their row norm factors)
__device__ __nv_bfloat162 g_x0bf [NN * DIM / 2];   // x0  * invsv[row]
__device__ __nv_bfloat162 g_x1abf[EE * DIM / 2];   // x1a * invse[row]
__device__ __nv_bfloat162 g_x0lbf[NN * DIM / 2];   // x0l * invsv[row]

// pre-split bf16 hi/lo weight planes
__device__ __nv_bfloat16 g_wh[W_TOTAL];
__device__ __nv_bfloat16 g_wl[W_TOTAL];

// ---------------- weight prepack (one launch) --------------------------------
__global__ __launch_bounds__(256) void prepack_w_kernel(
    const float* __restrict__ We, const float* __restrict__ Wn,
    const float* __restrict__ Wr, const float* __restrict__ W1,
    const float* __restrict__ W2)
{
    int i = blockIdx.x * blockDim.x + threadIdx.x;
    if (i >= W_TOTAL) return;
    const float* src; int off;
    if      (i < OFF_WN) { src = We; off = OFF_WE; }
    else if (i < OFF_WR) { src = Wn; off = OFF_WN; }
    else if (i < OFF_W1) { src = Wr; off = OFF_WR; }
    else if (i < OFF_W2) { src = W1; off = OFF_W1; }
    else                 { src = W2; off = OFF_W2; }
    float v = src[i - off];
    __nv_bfloat16 h = __float2bfloat16_rn(v);
    g_wh[i] = h;
    g_wl[i] = __float2bfloat16_rn(v - __bfloat162float(h));
}

// ---------------- sparse build ----------------------------------------------
__global__ __launch_bounds__(256) void build_csr_kernel(const float* __restrict__ H) {
    int gtid = blockIdx.x * blockDim.x + threadIdx.x;
    if (gtid < EE) g_ccnt[gtid] = 0;

    int warp = gtid >> 5;
    int lane = threadIdx.x & 31;
    if (warp >= NN) return;
    const float* row = H + (size_t)warp * EE;
    int base = 0;
    for (int it = 0; it < EE / 128; it++) {
        float4 v4 = *(const float4*)(row + it * 128 + lane * 4);
        float v[4] = {v4.x, v4.y, v4.z, v4.w};
#pragma unroll
        for (int j = 0; j < 4; j++) {
            unsigned m = __ballot_sync(0xffffffffu, v[j] != 0.0f);
            if (v[j] != 0.0f) {
                int pos = base + __popc(m & ((1u << lane) - 1u));
                if (pos < CAP_R) g_cols[warp * CAP_R + pos] = it * 128 + lane * 4 + j;
            }
            base += __popc(m);
        }
    }
    if (lane == 0) {
        g_rcnt[warp]  = min(base, CAP_R);
        g_invsv[warp] = rsqrtf(fmaxf((float)base, 1.0f));
    }
}

// Fused: CSR->CSC scatter + x0 -> bf16 (pre-scaled by invsv[row]).
__global__ void scatter_cvt_kernel(const float* __restrict__ x0) {
    int tid = blockIdx.x * blockDim.x + threadIdx.x;   // NN*CAP_R == NN*DIM/2 threads
    int row = tid >> 7;                                // 128 pairs per row == CAP_R
    float2 p = *(const float2*)(x0 + (size_t)tid * 2);
    float s = g_invsv[row];
    g_x0bf[tid] = __floats2bfloat162_rn(p.x * s, p.y * s);

    int k = tid & (CAP_R - 1);
    if (k < g_rcnt[row]) {
        int col = g_cols[row * CAP_R + k];
        int p2 = atomicAdd(&g_ccnt[col], 1);
        if (p2 < CAP_C) g_rows[col * CAP_C + p2] = row;
    }
}

// ---------------- SpMM gathers (pre-scaled bf16 sources) ---------------------
// out[e,:] = invse[e] * sum_{i in edge e} src[i,:]    (src already * invsv)
// Also publishes invse[e] (folded former finalize_cols_kernel).
__global__ __launch_bounds__(128) void spmm_edges_kernel(const __nv_bfloat162* __restrict__ src,
                                                         float* __restrict__ out) {
    int e = blockIdx.x;
    int t = threadIdx.x;
    int craw = g_ccnt[e];
    float se = rsqrtf(fmaxf((float)craw, 1.0f));
    if (t == 0) g_invse[e] = se;
    int cnt = min(craw, CAP_C);
    const int* lst = &g_rows[e * CAP_C];
    float2 a0 = {0.f,0.f}, a1 = {0.f,0.f}, a2 = {0.f,0.f}, a3 = {0.f,0.f};
    int k = 0;
    for (; k + 8 <= cnt; k += 8) {
        int4 l0 = *(const int4*)(lst + k);
        int4 l1 = *(const int4*)(lst + k + 4);
        float2 f0 = __bfloat1622float2(src[(unsigned)(l0.x * 128 + t)]);
        float2 f1 = __bfloat1622float2(src[(unsigned)(l0.y * 128 + t)]);
        float2 f2 = __bfloat1622float2(src[(unsigned)(l0.z * 128 + t)]);
        float2 f3 = __bfloat1622float2(src[(unsigned)(l0.w * 128 + t)]);
        float2 f4 = __bfloat1622float2(src[(unsigned)(l1.x * 128 + t)]);
        float2 f5 = __bfloat1622float2(src[(unsigned)(l1.y * 128 + t)]);
        float2 f6 = __bfloat1622float2(src[(unsigned)(l1.z * 128 + t)]);
        float2 f7 = __bfloat1622float2(src[(unsigned)(l1.w * 128 + t)]);
        a0.x += f0.x + f4.x; a0.y += f0.y + f4.y;
        a1.x += f1.x + f5.x; a1.y += f1.y + f5.y;
        a2.x += f2.x + f6.x; a2.y += f2.y + f6.y;
        a3.x += f3.x + f7.x; a3.y += f3.y + f7.y;
    }
    for (; k < cnt; k++) {
        float2 f0 = __bfloat1622float2(src[(unsigned)(lst[k] * 128 + t)]);
        a0.x += f0.x; a0.y += f0.y;
    }
    float2 o = make_float2(((a0.x + a1.x) + (a2.x + a3.x)) * se,
                           ((a0.y + a1.y) + (a2.y + a3.y)) * se);
    *(float2*)(out + (size_t)e * DIM + t * 2) = o;
}

// out[i,:] = invsv[i] * sum_{e in node i} src[e,:]    (src already * invse)
__global__ __launch_bounds__(128) void spmm_nodes_kernel(const __nv_bfloat162* __restrict__ src,
                                                         float* __restrict__ out) {
    int i = blockIdx.x;
    int t = threadIdx.x;
    int cnt = g_rcnt[i];
    const int* lst = &g_cols[i * CAP_R];
    float2 a0 = {0.f,0.f}, a1 = {0.f,0.f}, a2 = {0.f,0.f}, a3 = {0.f,0.f};
    int k = 0;
    for (; k + 8 <= cnt; k += 8) {
        int4 l0 = *(const int4*)(lst + k);
        int4 l1 = *(const int4*)(lst + k + 4);
        float2 f0 = __bfloat1622float2(src[(unsigned)(l0.x * 128 + t)]);
        float2 f1 = __bfloat1622float2(src[(unsigned)(l0.y * 128 + t)]);
        float2 f2 = __bfloat1622float2(src[(unsigned)(l0.z * 128 + t)]);
        float2 f3 = __bfloat1622float2(src[(unsigned)(l0.w * 128 + t)]);
        float2 f4 = __bfloat1622float2(src[(unsigned)(l1.x * 128 + t)]);
        float2 f5 = __bfloat1622float2(src[(unsigned)(l1.y * 128 + t)]);
        float2 f6 = __bfloat1622float2(src[(unsigned)(l1.z * 128 + t)]);
        float2 f7 = __bfloat1622float2(src[(unsigned)(l1.w * 128 + t)]);
        a0.x += f0.x + f4.x; a0.y += f0.y + f4.y;
        a1.x += f1.x + f5.x; a1.y += f1.y + f5.y;
        a2.x += f2.x + f6.x; a2.y += f2.y + f6.y;
        a3.x += f3.x + f7.x; a3.y += f3.y + f7.y;
    }
    for (; k < cnt; k++) {
        float2 f0 = __bfloat1622float2(src[(unsigned)(lst[k] * 128 + t)]);
        a0.x += f0.x; a0.y += f0.y;
    }
    float sv = g_invsv[i];
    float2 o = make_float2(((a0.x + a1.x) + (a2.x + a3.x)) * sv,
                           ((a0.y + a1.y) + (a2.y + a3.y)) * sv);
    *(float2*)(out + (size_t)i * DIM + t * 2) = o;
}

// ---------------- tensor-core GEMM: A fp32 split in-kernel, B pre-split -----
__device__ __forceinline__ void mma_bf16(float* c, const unsigned* a, const unsigned* b) {
    asm volatile(
        "mma.sync.aligned.m16n8k16.row.col.f32.bf16.bf16.f32 "
        "{%0,%1,%2,%3}, {%4,%5,%6,%7}, {%8,%9}, {%0,%1,%2,%3};\n"
        : "+f"(c[0]), "+f"(c[1]), "+f"(c[2]), "+f"(c[3])
        : "r"(a[0]), "r"(a[1]), "r"(a[2]), "r"(a[3]), "r"(b[0]), "r"(b[1]));
}

template<bool RESID, bool GELU>
__global__ __launch_bounds__(256) void gemm_tc_kernel(
    const float* __restrict__ A,
    const __nv_bfloat16* __restrict__ Bh_g, const __nv_bfloat16* __restrict__ Bl_g,
    const float* __restrict__ bias, const float* __restrict__ resid,
    const float* __restrict__ gate, float* __restrict__ C,
    __nv_bfloat162* __restrict__ bfc, const float* __restrict__ rowscale,
    int M, int N, int K)
{
    __shared__ unsigned Ah[128][20];
    __shared__ unsigned Al[128][20];
    __shared__ unsigned Bh[128][20];
    __shared__ unsigned Bl[128][20];

    const int tid  = threadIdx.x;
    const int warp = tid >> 5;
    const int lane = tid & 31;
    const int grp  = lane >> 2;
    const int qd   = lane & 3;
    const int m0 = blockIdx.y * 128;
    const int n0 = blockIdx.x * 128;
    const int warpM = (warp >> 2) * 64;
    const int warpN = (warp & 3) * 32;

    float acc[4][4][4];
#pragma unroll
    for (int mf = 0; mf < 4; mf++)
#pragma unroll
        for (int nf = 0; nf < 4; nf++)
#pragma unroll
            for (int r = 0; r < 4; r++) acc[mf][nf][r] = 0.0f;

    float4 ra[4];
    ushort4 rbh[4], rbl[4];
    const int a_m  = tid >> 3;
    const int a_k4 = (tid & 7) * 4;
    const int b_k  = tid >> 5;
    const int b_n4 = (tid & 31) * 4;

#pragma unroll
    for (int i = 0; i < 4; i++)
        ra[i] = *(const float4*)(A + (size_t)(m0 + a_m + i * 32) * K + a_k4);
#pragma unroll
    for (int i = 0; i < 4; i++) {
        size_t off = (size_t)(b_k + i * 8) * N + n0 + b_n4;
        rbh[i] = *(const ushort4*)(Bh_g + off);
        rbl[i] = *(const ushort4*)(Bl_g + off);
    }

    const int ntiles = K / 32;
    for (int t = 0; t < ntiles; t++) {
        __nv_bfloat16* bh16 = (__nv_bfloat16*)&Bh[0][0];   // pitch 40
        __nv_bfloat16* bl16 = (__nv_bfloat16*)&Bl[0][0];
#pragma unroll
        for (int i = 0; i < 4; i++) {
            float4 v = ra[i];
            __nv_bfloat162 h01 = __floats2bfloat162_rn(v.x, v.y);
            __nv_bfloat162 h23 = __floats2bfloat162_rn(v.z, v.w);
            float2 f01 = __bfloat1622float2(h01);
            float2 f23 = __bfloat1622float2(h23);
            __nv_bfloat162 l01 = __floats2bfloat162_rn(v.x - f01.x, v.y - f01.y);
            __nv_bfloat162 l23 = __floats2bfloat162_rn(v.z - f23.x, v.w - f23.y);
            int m = a_m + i * 32;
            Ah[m][a_k4 / 2]     = *(unsigned*)&h01;
            Ah[m][a_k4 / 2 + 1] = *(unsigned*)&h23;
            Al[m][a_k4 / 2]     = *(unsigned*)&l01;
            Al[m][a_k4 / 2 + 1] = *(unsigned*)&l23;
        }
#pragma unroll
        for (int i = 0; i < 4; i++) {
            int kk = b_k + i * 8;
            const unsigned short* ph = (const unsigned short*)&rbh[i];
            const unsigned short* pl = (const unsigned short*)&rbl[i];
#pragma unroll
            for (int j = 0; j < 4; j++) {
                ((unsigned short*)bh16)[(b_n4 + j) * 40 + kk] = ph[j];
                ((unsigned short*)bl16)[(b_n4 + j) * 40 + kk] = pl[j];
            }
        }
        __syncthreads();

        if (t + 1 < ntiles) {
            int k0 = (t + 1) * 32;
#pragma unroll
            for (int i = 0; i < 4; i++)
                ra[i] = *(const float4*)(A + (size_t)(m0 + a_m + i * 32) * K + k0 + a_k4);
#pragma unroll
            for (int i = 0; i < 4; i++) {
                size_t off = (size_t)(k0 + b_k + i * 8) * N + n0 + b_n4;
                rbh[i] = *(const ushort4*)(Bh_g + off);
                rbl[i] = *(const ushort4*)(Bl_g + off);
            }
        }

#pragma unroll
        for (int ks = 0; ks < 2; ks++) {
            const int kb = ks * 8;
            unsigned afh[4][4], afl[4][4], bf[4][2];
#pragma unroll
            for (int mf = 0; mf < 4; mf++) {
                int mrow = warpM + mf * 16 + grp;
                afh[mf][0] = Ah[mrow][kb + qd];
                afh[mf][1] = Ah[mrow + 8][kb + qd];
                afh[mf][2] = Ah[mrow][kb + qd + 4];
                afh[mf][3] = Ah[mrow + 8][kb + qd + 4];
                afl[mf][0] = Al[mrow][kb + qd];
                afl[mf][1] = Al[mrow + 8][kb + qd];
                afl[mf][2] = Al[mrow][kb + qd + 4];
                afl[mf][3] = Al[mrow + 8][kb + qd + 4];
            }
#pragma unroll
            for (int nf = 0; nf < 4; nf++) {
                int nrow = warpN + nf * 8 + grp;
                bf[nf][0] = Bh[nrow][kb + qd];
                bf[nf][1] = Bh[nrow][kb + qd + 4];
            }
#pragma unroll
            for (int mf = 0; mf < 4; mf++)
#pragma unroll
                for (int nf = 0; nf < 4; nf++) {
                    mma_bf16(acc[mf][nf], afh[mf], bf[nf]);
                    mma_bf16(acc[mf][nf], afl[mf], bf[nf]);
                }
#pragma unroll
            for (int nf = 0; nf < 4; nf++) {
                int nrow = warpN + nf * 8 + grp;
                bf[nf][0] = Bl[nrow][kb + qd];
                bf[nf][1] = Bl[nrow][kb + qd + 4];
            }
#pragma unroll
            for (int mf = 0; mf < 4; mf++)
#pragma unroll
                for (int nf = 0; nf < 4; nf++)
                    mma_bf16(acc[mf][nf], afh[mf], bf[nf]);
        }
        __syncthreads();
    }

    float alpha = 1.0f;
    if (!GELU && gate != nullptr) alpha = tanhf(gate[0]);

#pragma unroll
    for (int mf = 0; mf < 4; mf++) {
#pragma unroll
        for (int nf = 0; nf < 4; nf++) {
            int col = n0 + warpN + nf * 8 + 2 * qd;
            float bv0 = bias[col], bv1 = bias[col + 1];
            int r0 = m0 + warpM + mf * 16 + grp;
#pragma unroll
            for (int half = 0; half < 2; half++) {
                int row = r0 + half * 8;
                float v0 = acc[mf][nf][half * 2 + 0] + bv0;
                float v1 = acc[mf][nf][half * 2 + 1] + bv1;
                if (GELU) {
                    v0 = 0.5f * v0 * (1.0f + erff(v0 * 0.7071067811865476f));
                    v1 = 0.5f * v1 * (1.0f + erff(v1 * 0.7071067811865476f));
                } else {
                    v0 *= alpha; v1 *= alpha;
                }
                size_t base = (size_t)row * N + col;
                if (RESID) {
                    float2 r = *(const float2*)(resid + base);
                    v0 += r.x; v1 += r.y;
                }
                *(float2*)(C + base) = make_float2(v0, v1);
                if (bfc) {
                    float s = rowscale ? rowscale[row] : 1.0f;
                    bfc[base >> 1] = __floats2bfloat162_rn(v0 * s, v1 * s);
                }
            }
        }
    }
}

// ---------------- fused double LayerNorm -------------------------------------
__device__ __forceinline__ float block_sum_256(float v, float* sm) {
#pragma unroll
    for (int o = 16; o > 0; o >>= 1) v += __shfl_xor_sync(0xffffffffu, v, o);
    int w = threadIdx.x >> 5, lane = threadIdx.x & 31;
    if (lane == 0) sm[w] = v;
    __syncthreads();
    if (w == 0) {
        float s = (lane < 8) ? sm[lane] : 0.0f;
#pragma unroll
        for (int o = 4; o > 0; o >>= 1) s += __shfl_xor_sync(0xffffffffu, s, o);
        if (lane == 0) sm[0] = s;
    }
    __syncthreads();
    float r = sm[0];
    __syncthreads();
    return r;
}

__global__ __launch_bounds__(DIM) void ln_double_kernel(
    const float* __restrict__ g1, const float* __restrict__ b1,
    const float* __restrict__ g2, const float* __restrict__ b2)
{
    __shared__ float sm[8];
    int r = blockIdx.x, t = threadIdx.x;
    float v = g_u[(size_t)r * DIM + t];
    float mean = block_sum_256(v, sm) * (1.0f / DIM);
    float d = v - mean;
    float var = block_sum_256(d * d, sm) * (1.0f / DIM);
    float y = d * rsqrtf(var + LN_EPS) * g1[t] + b1[t];
    {
        float sv = g_invsv[r];
        float y_hi = __shfl_xor_sync(0xffffffffu, y, 1);
        if ((t & 1) == 0)
            g_x0lbf[((size_t)r * DIM + t) >> 1] = __floats2bfloat162_rn(y * sv, y_hi * sv);
    }
    float m2 = block_sum_256(y, sm) * (1.0f / DIM);
    float d2 = y - m2;
    float v2 = block_sum_256(d2 * d2, sm) * (1.0f / DIM);
    g_x0g[(size_t)r * DIM + t] = d2 * rsqrtf(v2 + LN_EPS) * g2[t] + b2[t];
}

// ---------------- driver -----------------------------------------------------
extern "C" void kernel_launch(void* const* d_in, const int* in_sizes, int n_in,
                              void* d_out, int out_size) {
    const float* x0   = (const float*)d_in[0];
    const float* x1   = (const float*)d_in[1];
    const float* H    = (const float*)d_in[2];
    const float* Wn   = (const float*)d_in[3];
    const float* bn   = (const float*)d_in[4];
    const float* We   = (const float*)d_in[5];
    const float* be   = (const float*)d_in[6];
    const float* Wr   = (const float*)d_in[7];
    const float* br   = (const float*)d_in[8];
    const float* W1   = (const float*)d_in[9];
    const float* b1   = (const float*)d_in[10];
    const float* W2   = (const float*)d_in[11];
    const float* b2   = (const float*)d_in[12];
    const float* ln1g = (const float*)d_in[13];
    const float* ln1b = (const float*)d_in[14];
    const float* ln2g = (const float*)d_in[15];
    const float* ln2b = (const float*)d_in[16];
    const float* gl   = (const float*)d_in[17];
    const float* gr   = (const float*)d_in[18];

    float* out_x0 = (float*)d_out;
    float* out_x1 = (float*)d_out + (size_t)NN * DIM;

    float *p_tmpE, *p_x1a, *p_msg, *p_u, *p_x0g, *p_ret, *p_h, *p_invse;
    __nv_bfloat162 *p_x0bf, *p_x1abf, *p_x0lbf;
    __nv_bfloat16 *p_wh, *p_wl;
    cudaGetSymbolAddress((void**)&p_tmpE, g_tmpE);
    cudaGetSymbolAddress((void**)&p_x1a,  g_x1a);
    cudaGetSymbolAddress((void**)&p_msg,  g_msg);
    cudaGetSymbolAddress((void**)&p_u,    g_u);
    cudaGetSymbolAddress((void**)&p_x0g,  g_x0g);
    cudaGetSymbolAddress((void**)&p_ret,  g_ret);
    cudaGetSymbolAddress((void**)&p_h,    g_h);
    cudaGetSymbolAddress((void**)&p_invse, g_invse);
    cudaGetSymbolAddress((void**)&p_x0bf,  g_x0bf);
    cudaGetSymbolAddress((void**)&p_x1abf, g_x1abf);
    cudaGetSymbolAddress((void**)&p_x0lbf, g_x0lbf);
    cudaGetSymbolAddress((void**)&p_wh, g_wh);
    cudaGetSymbolAddress((void**)&p_wl, g_wl);

    // 1) weight prepack ; 2) sparse build ; 3) scatter + x0->bf16(*invsv)
    prepack_w_kernel<<<(W_TOTAL + 255) / 256, 256>>>(We, Wn, Wr, W1, W2);
    build_csr_kernel<<<NN / 8, 256>>>(H);
    scatter_cvt_kernel<<<(NN * CAP_R) / 256, 256>>>(x0);

    // 4) tmpE = H_norm^T @ x0   (also publishes invse)  <-- ncu profiled slot
    spmm_edges_kernel<<<EE, 128>>>(p_x0bf, p_tmpE);
    // 5) x1a = x1 + tmpE @ We + be   (+ bf16 copy scaled by invse)
    gemm_tc_kernel<true, false><<<dim3(DIM / 128, EE / 128), 256>>>(
        p_tmpE, p_wh + OFF_WE, p_wl + OFF_WE, be, x1, nullptr, p_x1a, p_x1abf, p_invse,
        EE, DIM, DIM);
    // 6) msg = H_norm @ x1a
    spmm_nodes_kernel<<<NN, 128>>>(p_x1abf, p_msg);
    // 7) u = x0 + tanh(gl) * (msg @ Wn + bn)
    gemm_tc_kernel<true, false><<<dim3(DIM / 128, NN / 128), 256>>>(
        p_msg, p_wh + OFF_WN, p_wl + OFF_WN, bn, x0, gl, p_u, nullptr, nullptr,
        NN, DIM, DIM);
    // 8) LN1 (bf16*invsv out) + LN2 (fp32 out)
    ln_double_kernel<<<NN, DIM>>>(ln1g, ln1b, ln2g, ln2b);
    // 9) ret = H_norm^T @ x0_local
    spmm_edges_kernel<<<EE, 128>>>(p_x0lbf, p_ret);
    // 10) x1_out = x1a + tanh(gr) * (ret @ Wr + br)
    gemm_tc_kernel<true, false><<<dim3(DIM / 128, EE / 128), 256>>>(
        p_ret, p_wh + OFF_WR, p_wl + OFF_WR, br, p_x1a, gr, out_x1, nullptr, nullptr,
        EE, DIM, DIM);
    // 11) h = gelu(x0_global @ W1 + b1)
    gemm_tc_kernel<false, true><<<dim3((2 * DIM) / 128, NN / 128), 256>>>(
        p_x0g, p_wh + OFF_W1, p_wl + OFF_W1, b1, nullptr, nullptr, p_h, nullptr, nullptr,
        NN, 2 * DIM, DIM);
    // 12) x0_out = x0_global + h @ W2 + b2
    gemm_tc_kernel<true, false><<<dim3(DIM / 128, NN / 128), 256>>>(
        p_h, p_wh + OFF_W2, p_wl + OFF_W2, b2, p_x0g, nullptr, out_x0, nullptr, nullptr,
        NN, DIM, 2 * DIM);

    (void)in_sizes; (void)n_in; (void)out_size;
}

// round 6
// speedup vs baseline: 1.1597x; 1.0478x over previous
#include <cuda_runtime.h>
#include <cuda_bf16.h>
#include <math.h>

// Problem constants
#define NN   16384
#define EE   8192
#define DIM  256
#define CAP_R 128
#define CAP_C 192
#define LN_EPS 1e-5f

// Weight-plane offsets (elements) inside g_wh / g_wl
#define OFF_WE 0
#define OFF_WN 65536
#define OFF_WR 131072
#define OFF_W1 196608
#define OFF_W2 327680
#define W_TOTAL 458752

// ---------------- static device scratch (no allocations allowed) ------------
__device__ int   g_cols[NN * CAP_R];
__device__ int   g_rows[EE * CAP_C];
__device__ int   g_rcnt[NN];
__device__ int   g_ccnt[EE];
__device__ float g_invsv[NN];
__device__ float g_invse[EE];

__device__ float g_tmpE[EE * DIM];
__device__ float g_x1a [EE * DIM];
__device__ float g_msg [NN * DIM];
__device__ float g_u   [NN * DIM];
__device__ float g_x0g [NN * DIM];
__device__ float g_ret [EE * DIM];
__device__ float g_h   [NN * 2 * DIM];

// bf16 gather sources for the SpMMs (pre-scaled by their row norm factors)
__device__ __nv_bfloat162 g_x0bf [NN * DIM / 2];   // x0  * invsv[row]
__device__ __nv_bfloat162 g_x1abf[EE * DIM / 2];   // x1a * invse[row]
__device__ __nv_bfloat162 g_x0lbf[NN * DIM / 2];   // x0l * invsv[row]

// pre-split bf16 hi/lo weight planes
__device__ __nv_bfloat16 g_wh[W_TOTAL];
__device__ __nv_bfloat16 g_wl[W_TOTAL];

// ---------------- weight prepack (3 launches, so build_csr lands in ncu slot)
__global__ __launch_bounds__(256) void prepack3_kernel(
    const float* __restrict__ We, const float* __restrict__ Wn,
    const float* __restrict__ Wr)
{
    int i = blockIdx.x * blockDim.x + threadIdx.x;   // < 3*65536
    const float* src; int off;
    if      (i < OFF_WN) { src = We; off = OFF_WE; }
    else if (i < OFF_WR) { src = Wn; off = OFF_WN; }
    else                 { src = Wr; off = OFF_WR; }
    float v = src[i - off];
    __nv_bfloat16 h = __float2bfloat16_rn(v);
    g_wh[i] = h;
    g_wl[i] = __float2bfloat16_rn(v - __bfloat162float(h));
}

__global__ __launch_bounds__(256) void prepack1_kernel(
    const float* __restrict__ W, int off, int count)
{
    int i = blockIdx.x * blockDim.x + threadIdx.x;
    if (i >= count) return;
    float v = W[i];
    __nv_bfloat16 h = __float2bfloat16_rn(v);
    g_wh[off + i] = h;
    g_wl[off + i] = __float2bfloat16_rn(v - __bfloat162float(h));
}

// ---------------- sparse build ----------------------------------------------
__global__ __launch_bounds__(256) void build_csr_kernel(const float* __restrict__ H) {
    int gtid = blockIdx.x * blockDim.x + threadIdx.x;
    if (gtid < EE) g_ccnt[gtid] = 0;

    int warp = gtid >> 5;
    int lane = threadIdx.x & 31;
    if (warp >= NN) return;
    const float* row = H + (size_t)warp * EE;
    int base = 0;
    for (int it = 0; it < EE / 128; it++) {
        float4 v4 = *(const float4*)(row + it * 128 + lane * 4);
        float v[4] = {v4.x, v4.y, v4.z, v4.w};
#pragma unroll
        for (int j = 0; j < 4; j++) {
            unsigned m = __ballot_sync(0xffffffffu, v[j] != 0.0f);
            if (v[j] != 0.0f) {
                int pos = base + __popc(m & ((1u << lane) - 1u));
                if (pos < CAP_R) g_cols[warp * CAP_R + pos] = it * 128 + lane * 4 + j;
            }
            base += __popc(m);
        }
    }
    if (lane == 0) {
        g_rcnt[warp]  = min(base, CAP_R);
        g_invsv[warp] = rsqrtf(fmaxf((float)base, 1.0f));
    }
}

// Fused: CSR->CSC scatter + x0 -> bf16 (pre-scaled by invsv[row]).
__global__ void scatter_cvt_kernel(const float* __restrict__ x0) {
    int tid = blockIdx.x * blockDim.x + threadIdx.x;   // NN*CAP_R == NN*DIM/2 threads
    int row = tid >> 7;
    float2 p = *(const float2*)(x0 + (size_t)tid * 2);
    float s = g_invsv[row];
    g_x0bf[tid] = __floats2bfloat162_rn(p.x * s, p.y * s);

    int k = tid & (CAP_R - 1);
    if (k < g_rcnt[row]) {
        int col = g_cols[row * CAP_R + k];
        int p2 = atomicAdd(&g_ccnt[col], 1);
        if (p2 < CAP_C) g_rows[col * CAP_C + p2] = row;
    }
}

// ---------------- SpMM gathers: warp-per-row, LDG.64 (bf16x4) ---------------
// Each lane covers 8 dims via two uint2 loads. Accumulate fp32.
__device__ __forceinline__ void acc8(float* a, uint2 q0, uint2 q1) {
    float2 f;
    f = __bfloat1622float2(*(__nv_bfloat162*)&q0.x); a[0] += f.x; a[1] += f.y;
    f = __bfloat1622float2(*(__nv_bfloat162*)&q0.y); a[2] += f.x; a[3] += f.y;
    f = __bfloat1622float2(*(__nv_bfloat162*)&q1.x); a[4] += f.x; a[5] += f.y;
    f = __bfloat1622float2(*(__nv_bfloat162*)&q1.y); a[6] += f.x; a[7] += f.y;
}

// out[e,:] = invse[e] * sum_{i in edge e} src[i,:]   (src already * invsv)
// Also publishes invse[e] (folded finalize).
__global__ __launch_bounds__(256) void spmm_edges_kernel(const uint2* __restrict__ src,
                                                         float* __restrict__ out) {
    int e    = blockIdx.x * 8 + (threadIdx.x >> 5);
    int lane = threadIdx.x & 31;
    int craw = g_ccnt[e];
    float se = rsqrtf(fmaxf((float)craw, 1.0f));
    if (lane == 0) g_invse[e] = se;
    int cnt = min(craw, CAP_C);
    const int* lst = &g_rows[e * CAP_C];
    const int lx = lane << 1;          // uint2 index within row (64 per row)
    float a[8];
#pragma unroll
    for (int r = 0; r < 8; r++) a[r] = 0.0f;
    int k = 0;
    for (; k + 4 <= cnt; k += 4) {
        int4 l = *(const int4*)(lst + k);
        const uint2* p0 = src + ((unsigned)l.x << 6) + lx;
        const uint2* p1 = src + ((unsigned)l.y << 6) + lx;
        const uint2* p2 = src + ((unsigned)l.z << 6) + lx;
        const uint2* p3 = src + ((unsigned)l.w << 6) + lx;
        uint2 q00 = p0[0], q01 = p0[1];
        uint2 q10 = p1[0], q11 = p1[1];
        uint2 q20 = p2[0], q21 = p2[1];
        uint2 q30 = p3[0], q31 = p3[1];
        acc8(a, q00, q01);
        acc8(a, q10, q11);
        acc8(a, q20, q21);
        acc8(a, q30, q31);
    }
    for (; k < cnt; k++) {
        const uint2* p0 = src + ((unsigned)lst[k] << 6) + lx;
        acc8(a, p0[0], p0[1]);
    }
    float4 o0 = make_float4(a[0] * se, a[1] * se, a[2] * se, a[3] * se);
    float4 o1 = make_float4(a[4] * se, a[5] * se, a[6] * se, a[7] * se);
    float* op = out + (size_t)e * DIM + lane * 8;
    *(float4*)(op)     = o0;
    *(float4*)(op + 4) = o1;
}

// out[i,:] = invsv[i] * sum_{e in node i} src[e,:]   (src already * invse)
__global__ __launch_bounds__(256) void spmm_nodes_kernel(const uint2* __restrict__ src,
                                                         float* __restrict__ out) {
    int i    = blockIdx.x * 8 + (threadIdx.x >> 5);
    int lane = threadIdx.x & 31;
    int cnt = g_rcnt[i];
    const int* lst = &g_cols[i * CAP_R];
    const int lx = lane << 1;
    float a[8];
#pragma unroll
    for (int r = 0; r < 8; r++) a[r] = 0.0f;
    int k = 0;
    for (; k + 4 <= cnt; k += 4) {
        int4 l = *(const int4*)(lst + k);
        const uint2* p0 = src + ((unsigned)l.x << 6) + lx;
        const uint2* p1 = src + ((unsigned)l.y << 6) + lx;
        const uint2* p2 = src + ((unsigned)l.z << 6) + lx;
        const uint2* p3 = src + ((unsigned)l.w << 6) + lx;
        uint2 q00 = p0[0], q01 = p0[1];
        uint2 q10 = p1[0], q11 = p1[1];
        uint2 q20 = p2[0], q21 = p2[1];
        uint2 q30 = p3[0], q31 = p3[1];
        acc8(a, q00, q01);
        acc8(a, q10, q11);
        acc8(a, q20, q21);
        acc8(a, q30, q31);
    }
    for (; k < cnt; k++) {
        const uint2* p0 = src + ((unsigned)lst[k] << 6) + lx;
        acc8(a, p0[0], p0[1]);
    }
    float sv = g_invsv[i];
    float4 o0 = make_float4(a[0] * sv, a[1] * sv, a[2] * sv, a[3] * sv);
    float4 o1 = make_float4(a[4] * sv, a[5] * sv, a[6] * sv, a[7] * sv);
    float* op = out + (size_t)i * DIM + lane * 8;
    *(float4*)(op)     = o0;
    *(float4*)(op + 4) = o1;
}

// ---------------- tensor-core GEMM: A fp32 split in-kernel, B pre-split -----
__device__ __forceinline__ void mma_bf16(float* c, const unsigned* a, const unsigned* b) {
    asm volatile(
        "mma.sync.aligned.m16n8k16.row.col.f32.bf16.bf16.f32 "
        "{%0,%1,%2,%3}, {%4,%5,%6,%7}, {%8,%9}, {%0,%1,%2,%3};\n"
        : "+f"(c[0]), "+f"(c[1]), "+f"(c[2]), "+f"(c[3])
        : "r"(a[0]), "r"(a[1]), "r"(a[2]), "r"(a[3]), "r"(b[0]), "r"(b[1]));
}

template<bool RESID, bool GELU>
__global__ __launch_bounds__(256) void gemm_tc_kernel(
    const float* __restrict__ A,
    const __nv_bfloat16* __restrict__ Bh_g, const __nv_bfloat16* __restrict__ Bl_g,
    const float* __restrict__ bias, const float* __restrict__ resid,
    const float* __restrict__ gate, float* __restrict__ C,
    __nv_bfloat162* __restrict__ bfc, const float* __restrict__ rowscale,
    int M, int N, int K)
{
    __shared__ unsigned Ah[128][20];
    __shared__ unsigned Al[128][20];
    __shared__ unsigned Bh[128][20];
    __shared__ unsigned Bl[128][20];

    const int tid  = threadIdx.x;
    const int warp = tid >> 5;
    const int lane = tid & 31;
    const int grp  = lane >> 2;
    const int qd   = lane & 3;
    const int m0 = blockIdx.y * 128;
    const int n0 = blockIdx.x * 128;
    const int warpM = (warp >> 2) * 64;
    const int warpN = (warp & 3) * 32;

    float acc[4][4][4];
#pragma unroll
    for (int mf = 0; mf < 4; mf++)
#pragma unroll
        for (int nf = 0; nf < 4; nf++)
#pragma unroll
            for (int r = 0; r < 4; r++) acc[mf][nf][r] = 0.0f;

    float4 ra[4];
    ushort4 rbh[4], rbl[4];
    const int a_m  = tid >> 3;
    const int a_k4 = (tid & 7) * 4;
    const int b_k  = tid >> 5;
    const int b_n4 = (tid & 31) * 4;

#pragma unroll
    for (int i = 0; i < 4; i++)
        ra[i] = *(const float4*)(A + (size_t)(m0 + a_m + i * 32) * K + a_k4);
#pragma unroll
    for (int i = 0; i < 4; i++) {
        size_t off = (size_t)(b_k + i * 8) * N + n0 + b_n4;
        rbh[i] = *(const ushort4*)(Bh_g + off);
        rbl[i] = *(const ushort4*)(Bl_g + off);
    }

    const int ntiles = K / 32;
    for (int t = 0; t < ntiles; t++) {
        __nv_bfloat16* bh16 = (__nv_bfloat16*)&Bh[0][0];
        __nv_bfloat16* bl16 = (__nv_bfloat16*)&Bl[0][0];
#pragma unroll
        for (int i = 0; i < 4; i++) {
            float4 v = ra[i];
            __nv_bfloat162 h01 = __floats2bfloat162_rn(v.x, v.y);
            __nv_bfloat162 h23 = __floats2bfloat162_rn(v.z, v.w);
            float2 f01 = __bfloat1622float2(h01);
            float2 f23 = __bfloat1622float2(h23);
            __nv_bfloat162 l01 = __floats2bfloat162_rn(v.x - f01.x, v.y - f01.y);
            __nv_bfloat162 l23 = __floats2bfloat162_rn(v.z - f23.x, v.w - f23.y);
            int m = a_m + i * 32;
            Ah[m][a_k4 / 2]     = *(unsigned*)&h01;
            Ah[m][a_k4 / 2 + 1] = *(unsigned*)&h23;
            Al[m][a_k4 / 2]     = *(unsigned*)&l01;
            Al[m][a_k4 / 2 + 1] = *(unsigned*)&l23;
        }
#pragma unroll
        for (int i = 0; i < 4; i++) {
            int kk = b_k + i * 8;
            const unsigned short* ph = (const unsigned short*)&rbh[i];
            const unsigned short* pl = (const unsigned short*)&rbl[i];
#pragma unroll
            for (int j = 0; j < 4; j++) {
                ((unsigned short*)bh16)[(b_n4 + j) * 40 + kk] = ph[j];
                ((unsigned short*)bl16)[(b_n4 + j) * 40 + kk] = pl[j];
            }
        }
        __syncthreads();

        if (t + 1 < ntiles) {
            int k0 = (t + 1) * 32;
#pragma unroll
            for (int i = 0; i < 4; i++)
                ra[i] = *(const float4*)(A + (size_t)(m0 + a_m + i * 32) * K + k0 + a_k4);
#pragma unroll
            for (int i = 0; i < 4; i++) {
                size_t off = (size_t)(k0 + b_k + i * 8) * N + n0 + b_n4;
                rbh[i] = *(const ushort4*)(Bh_g + off);
                rbl[i] = *(const ushort4*)(Bl_g + off);
            }
        }

#pragma unroll
        for (int ks = 0; ks < 2; ks++) {
            const int kb = ks * 8;
            unsigned afh[4][4], afl[4][4], bf[4][2];
#pragma unroll
            for (int mf = 0; mf < 4; mf++) {
                int mrow = warpM + mf * 16 + grp;
                afh[mf][0] = Ah[mrow][kb + qd];
                afh[mf][1] = Ah[mrow + 8][kb + qd];
                afh[mf][2] = Ah[mrow][kb + qd + 4];
                afh[mf][3] = Ah[mrow + 8][kb + qd + 4];
                afl[mf][0] = Al[mrow][kb + qd];
                afl[mf][1] = Al[mrow + 8][kb + qd];
                afl[mf][2] = Al[mrow][kb + qd + 4];
                afl[mf][3] = Al[mrow + 8][kb + qd + 4];
            }
#pragma unroll
            for (int nf = 0; nf < 4; nf++) {
                int nrow = warpN + nf * 8 + grp;
                bf[nf][0] = Bh[nrow][kb + qd];
                bf[nf][1] = Bh[nrow][kb + qd + 4];
            }
#pragma unroll
            for (int mf = 0; mf < 4; mf++)
#pragma unroll
                for (int nf = 0; nf < 4; nf++) {
                    mma_bf16(acc[mf][nf], afh[mf], bf[nf]);
                    mma_bf16(acc[mf][nf], afl[mf], bf[nf]);
                }
#pragma unroll
            for (int nf = 0; nf < 4; nf++) {
                int nrow = warpN + nf * 8 + grp;
                bf[nf][0] = Bl[nrow][kb + qd];
                bf[nf][1] = Bl[nrow][kb + qd + 4];
            }
#pragma unroll
            for (int mf = 0; mf < 4; mf++)
#pragma unroll
                for (int nf = 0; nf < 4; nf++)
                    mma_bf16(acc[mf][nf], afh[mf], bf[nf]);
        }
        __syncthreads();
    }

    float alpha = 1.0f;
    if (!GELU && gate != nullptr) alpha = tanhf(gate[0]);

#pragma unroll
    for (int mf = 0; mf < 4; mf++) {
#pragma unroll
        for (int nf = 0; nf < 4; nf++) {
            int col = n0 + warpN + nf * 8 + 2 * qd;
            float bv0 = bias[col], bv1 = bias[col + 1];
            int r0 = m0 + warpM + mf * 16 + grp;
#pragma unroll
            for (int half = 0; half < 2; half++) {
                int row = r0 + half * 8;
                float v0 = acc[mf][nf][half * 2 + 0] + bv0;
                float v1 = acc[mf][nf][half * 2 + 1] + bv1;
                if (GELU) {
                    v0 = 0.5f * v0 * (1.0f + erff(v0 * 0.7071067811865476f));
                    v1 = 0.5f * v1 * (1.0f + erff(v1 * 0.7071067811865476f));
                } else {
                    v0 *= alpha; v1 *= alpha;
                }
                size_t base = (size_t)row * N + col;
                if (RESID) {
                    float2 r = *(const float2*)(resid + base);
                    v0 += r.x; v1 += r.y;
                }
                *(float2*)(C + base) = make_float2(v0, v1);
                if (bfc) {
                    float s = rowscale ? rowscale[row] : 1.0f;
                    bfc[base >> 1] = __floats2bfloat162_rn(v0 * s, v1 * s);
                }
            }
        }
    }
}

// ---------------- fused double LayerNorm -------------------------------------
__device__ __forceinline__ float block_sum_256(float v, float* sm) {
#pragma unroll
    for (int o = 16; o > 0; o >>= 1) v += __shfl_xor_sync(0xffffffffu, v, o);
    int w = threadIdx.x >> 5, lane = threadIdx.x & 31;
    if (lane == 0) sm[w] = v;
    __syncthreads();
    if (w == 0) {
        float s = (lane < 8) ? sm[lane] : 0.0f;
#pragma unroll
        for (int o = 4; o > 0; o >>= 1) s += __shfl_xor_sync(0xffffffffu, s, o);
        if (lane == 0) sm[0] = s;
    }
    __syncthreads();
    float r = sm[0];
    __syncthreads();
    return r;
}

__global__ __launch_bounds__(DIM) void ln_double_kernel(
    const float* __restrict__ g1, const float* __restrict__ b1,
    const float* __restrict__ g2, const float* __restrict__ b2)
{
    __shared__ float sm[8];
    int r = blockIdx.x, t = threadIdx.x;
    float v = g_u[(size_t)r * DIM + t];
    float mean = block_sum_256(v, sm) * (1.0f / DIM);
    float d = v - mean;
    float var = block_sum_256(d * d, sm) * (1.0f / DIM);
    float y = d * rsqrtf(var + LN_EPS) * g1[t] + b1[t];
    {
        float sv = g_invsv[r];
        float y_hi = __shfl_xor_sync(0xffffffffu, y, 1);
        if ((t & 1) == 0)
            g_x0lbf[((size_t)r * DIM + t) >> 1] = __floats2bfloat162_rn(y * sv, y_hi * sv);
    }
    float m2 = block_sum_256(y, sm) * (1.0f / DIM);
    float d2 = y - m2;
    float v2 = block_sum_256(d2 * d2, sm) * (1.0f / DIM);
    g_x0g[(size_t)r * DIM + t] = d2 * rsqrtf(v2 + LN_EPS) * g2[t] + b2[t];
}

// ---------------- driver -----------------------------------------------------
extern "C" void kernel_launch(void* const* d_in, const int* in_sizes, int n_in,
                              void* d_out, int out_size) {
    const float* x0   = (const float*)d_in[0];
    const float* x1   = (const float*)d_in[1];
    const float* H    = (const float*)d_in[2];
    const float* Wn   = (const float*)d_in[3];
    const float* bn   = (const float*)d_in[4];
    const float* We   = (const float*)d_in[5];
    const float* be   = (const float*)d_in[6];
    const float* Wr   = (const float*)d_in[7];
    const float* br   = (const float*)d_in[8];
    const float* W1   = (const float*)d_in[9];
    const float* b1   = (const float*)d_in[10];
    const float* W2   = (const float*)d_in[11];
    const float* b2   = (const float*)d_in[12];
    const float* ln1g = (const float*)d_in[13];
    const float* ln1b = (const float*)d_in[14];
    const float* ln2g = (const float*)d_in[15];
    const float* ln2b = (const float*)d_in[16];
    const float* gl   = (const float*)d_in[17];
    const float* gr   = (const float*)d_in[18];

    float* out_x0 = (float*)d_out;
    float* out_x1 = (float*)d_out + (size_t)NN * DIM;

    float *p_tmpE, *p_x1a, *p_msg, *p_u, *p_x0g, *p_ret, *p_h, *p_invse;
    __nv_bfloat162 *p_x0bf, *p_x1abf, *p_x0lbf;
    __nv_bfloat16 *p_wh, *p_wl;
    cudaGetSymbolAddress((void**)&p_tmpE, g_tmpE);
    cudaGetSymbolAddress((void**)&p_x1a,  g_x1a);
    cudaGetSymbolAddress((void**)&p_msg,  g_msg);
    cudaGetSymbolAddress((void**)&p_u,    g_u);
    cudaGetSymbolAddress((void**)&p_x0g,  g_x0g);
    cudaGetSymbolAddress((void**)&p_ret,  g_ret);
    cudaGetSymbolAddress((void**)&p_h,    g_h);
    cudaGetSymbolAddress((void**)&p_invse, g_invse);
    cudaGetSymbolAddress((void**)&p_x0bf,  g_x0bf);
    cudaGetSymbolAddress((void**)&p_x1abf, g_x1abf);
    cudaGetSymbolAddress((void**)&p_x0lbf, g_x0lbf);
    cudaGetSymbolAddress((void**)&p_wh, g_wh);
    cudaGetSymbolAddress((void**)&p_wl, g_wl);

    // 1-3) weight prepack (split into 3 so build_csr is the 4th launch = ncu slot)
    prepack3_kernel<<<(3 * 65536) / 256, 256>>>(We, Wn, Wr);
    prepack1_kernel<<<(131072 + 255) / 256, 256>>>(W1, OFF_W1, 131072);
    prepack1_kernel<<<(131072 + 255) / 256, 256>>>(W2, OFF_W2, 131072);

    // 4) sparse build          <-- ncu profiled slot this round
    build_csr_kernel<<<NN / 8, 256>>>(H);
    // 5) scatter + x0->bf16(*invsv)
    scatter_cvt_kernel<<<(NN * CAP_R) / 256, 256>>>(x0);

    // 6) tmpE = H_norm^T @ x0   (publishes invse)
    spmm_edges_kernel<<<EE / 8, 256>>>((const uint2*)p_x0bf, p_tmpE);
    // 7) x1a = x1 + tmpE @ We + be   (+ bf16 copy scaled by invse)
    gemm_tc_kernel<true, false><<<dim3(DIM / 128, EE / 128), 256>>>(
        p_tmpE, p_wh + OFF_WE, p_wl + OFF_WE, be, x1, nullptr, p_x1a, p_x1abf, p_invse,
        EE, DIM, DIM);
    // 8) msg = H_norm @ x1a
    spmm_nodes_kernel<<<NN / 8, 256>>>((const uint2*)p_x1abf, p_msg);
    // 9) u = x0 + tanh(gl) * (msg @ Wn + bn)
    gemm_tc_kernel<true, false><<<dim3(DIM / 128, NN / 128), 256>>>(
        p_msg, p_wh + OFF_WN, p_wl + OFF_WN, bn, x0, gl, p_u, nullptr, nullptr,
        NN, DIM, DIM);
    // 10) LN1 (bf16*invsv out) + LN2 (fp32 out)
    ln_double_kernel<<<NN, DIM>>>(ln1g, ln1b, ln2g, ln2b);
    // 11) ret = H_norm^T @ x0_local
    spmm_edges_kernel<<<EE / 8, 256>>>((const uint2*)p_x0lbf, p_ret);
    // 12) x1_out = x1a + tanh(gr) * (ret @ Wr + br)
    gemm_tc_kernel<true, false><<<dim3(DIM / 128, EE / 128), 256>>>(
        p_ret, p_wh + OFF_WR, p_wl + OFF_WR, br, p_x1a, gr, out_x1, nullptr, nullptr,
        EE, DIM, DIM);
    // 13) h = gelu(x0_global @ W1 + b1)
    gemm_tc_kernel<false, true><<<dim3((2 * DIM) / 128, NN / 128), 256>>>(
        p_x0g, p_wh + OFF_W1, p_wl + OFF_W1, b1, nullptr, nullptr, p_h, nullptr, nullptr,
        NN, 2 * DIM, DIM);
    // 14) x0_out = x0_global + h @ W2 + b2
    gemm_tc_kernel<true, false><<<dim3(DIM / 128, NN / 128), 256>>>(
        p_h, p_wh + OFF_W2, p_wl + OFF_W2, b2, p_x0g, nullptr, out_x0, nullptr, nullptr,
        NN, DIM, 2 * DIM);

    (void)in_sizes; (void)n_in; (void)out_size;
}

// round 7
// speedup vs baseline: 1.7319x; 1.4934x over previous
#include <cuda_runtime.h>
#include <cuda_bf16.h>
#include <math.h>

// Problem constants
#define NN   16384
#define EE   8192
#define DIM  256
#define CAP_R 128
#define CAP_C 192
#define LN_EPS 1e-5f

// Weight-plane offsets (elements) inside g_wh / g_wl
#define OFF_WE 0
#define OFF_WN 65536
#define OFF_WR 131072
#define OFF_W1 196608
#define OFF_W2 327680
#define W_TOTAL 458752

// ---------------- static device scratch (no allocations allowed) ------------
__device__ int   g_cols[NN * CAP_R];
__device__ int   g_rows[EE * CAP_C];
__device__ int   g_rcnt[NN];
__device__ int   g_ccnt[EE];
__device__ float g_invsv[NN];
__device__ float g_invse[EE];

__device__ float g_tmpE[EE * DIM];
__device__ float g_x1a [EE * DIM];
__device__ float g_msg [NN * DIM];
__device__ float g_u   [NN * DIM];
__device__ float g_x0g [NN * DIM];
__device__ float g_ret [EE * DIM];
__device__ float g_h   [NN * 2 * DIM];

// bf16 gather sources for the SpMMs (pre-scaled by their row norm factors)
__device__ __nv_bfloat162 g_x0bf [NN * DIM / 2];
__device__ __nv_bfloat162 g_x1abf[EE * DIM / 2];
__device__ __nv_bfloat162 g_x0lbf[NN * DIM / 2];

// pre-split bf16 hi/lo weight planes
__device__ __nv_bfloat16 g_wh[W_TOTAL];
__device__ __nv_bfloat16 g_wl[W_TOTAL];

// ---------------- sparse build + weight prepack (fused; DRAM-bound) ---------
__global__ __launch_bounds__(256) void build_csr_kernel(
    const float* __restrict__ H,
    const float* __restrict__ We, const float* __restrict__ Wn,
    const float* __restrict__ Wr, const float* __restrict__ W1,
    const float* __restrict__ W2)
{
    int gtid = blockIdx.x * blockDim.x + threadIdx.x;
    if (gtid < EE) g_ccnt[gtid] = 0;
    if (gtid < W_TOTAL) {
        const float* src; int off;
        if      (gtid < OFF_WN) { src = We; off = OFF_WE; }
        else if (gtid < OFF_WR) { src = Wn; off = OFF_WN; }
        else if (gtid < OFF_W1) { src = Wr; off = OFF_WR; }
        else if (gtid < OFF_W2) { src = W1; off = OFF_W1; }
        else                    { src = W2; off = OFF_W2; }
        float v = src[gtid - off];
        __nv_bfloat16 h = __float2bfloat16_rn(v);
        g_wh[gtid] = h;
        g_wl[gtid] = __float2bfloat16_rn(v - __bfloat162float(h));
    }

    int warp = gtid >> 5;
    int lane = threadIdx.x & 31;
    if (warp >= NN) return;
    const float* row = H + (size_t)warp * EE;
    int base = 0;
    for (int it = 0; it < EE / 128; it++) {
        float4 v4 = *(const float4*)(row + it * 128 + lane * 4);
        float v[4] = {v4.x, v4.y, v4.z, v4.w};
#pragma unroll
        for (int j = 0; j < 4; j++) {
            unsigned m = __ballot_sync(0xffffffffu, v[j] != 0.0f);
            if (v[j] != 0.0f) {
                int pos = base + __popc(m & ((1u << lane) - 1u));
                if (pos < CAP_R) g_cols[warp * CAP_R + pos] = it * 128 + lane * 4 + j;
            }
            base += __popc(m);
        }
    }
    if (lane == 0) {
        g_rcnt[warp]  = min(base, CAP_R);
        g_invsv[warp] = rsqrtf(fmaxf((float)base, 1.0f));
    }
}

// Fused: CSR->CSC scatter + x0 -> bf16 (pre-scaled by invsv[row]).
__global__ void scatter_cvt_kernel(const float* __restrict__ x0) {
    int tid = blockIdx.x * blockDim.x + threadIdx.x;
    int row = tid >> 7;
    float2 p = *(const float2*)(x0 + (size_t)tid * 2);
    float s = g_invsv[row];
    g_x0bf[tid] = __floats2bfloat162_rn(p.x * s, p.y * s);

    int k = tid & (CAP_R - 1);
    if (k < g_rcnt[row]) {
        int col = g_cols[row * CAP_R + k];
        int p2 = atomicAdd(&g_ccnt[col], 1);
        if (p2 < CAP_C) g_rows[col * CAP_C + p2] = row;
    }
}

// ---------------- SpMM gathers: warp-per-row, LDG.64 (bf16x4) ---------------
__device__ __forceinline__ void acc8(float* a, uint2 q0, uint2 q1) {
    float2 f;
    f = __bfloat1622float2(*(__nv_bfloat162*)&q0.x); a[0] += f.x; a[1] += f.y;
    f = __bfloat1622float2(*(__nv_bfloat162*)&q0.y); a[2] += f.x; a[3] += f.y;
    f = __bfloat1622float2(*(__nv_bfloat162*)&q1.x); a[4] += f.x; a[5] += f.y;
    f = __bfloat1622float2(*(__nv_bfloat162*)&q1.y); a[6] += f.x; a[7] += f.y;
}

__global__ __launch_bounds__(256) void spmm_edges_kernel(const uint2* __restrict__ src,
                                                         float* __restrict__ out) {
    int e    = blockIdx.x * 8 + (threadIdx.x >> 5);
    int lane = threadIdx.x & 31;
    int craw = g_ccnt[e];
    float se = rsqrtf(fmaxf((float)craw, 1.0f));
    if (lane == 0) g_invse[e] = se;
    int cnt = min(craw, CAP_C);
    const int* lst = &g_rows[e * CAP_C];
    const int lx = lane << 1;
    float a[8];
#pragma unroll
    for (int r = 0; r < 8; r++) a[r] = 0.0f;
    int k = 0;
    for (; k + 4 <= cnt; k += 4) {
        int4 l = *(const int4*)(lst + k);
        const uint2* p0 = src + ((unsigned)l.x << 6) + lx;
        const uint2* p1 = src + ((unsigned)l.y << 6) + lx;
        const uint2* p2 = src + ((unsigned)l.z << 6) + lx;
        const uint2* p3 = src + ((unsigned)l.w << 6) + lx;
        uint2 q00 = p0[0], q01 = p0[1];
        uint2 q10 = p1[0], q11 = p1[1];
        uint2 q20 = p2[0], q21 = p2[1];
        uint2 q30 = p3[0], q31 = p3[1];
        acc8(a, q00, q01);
        acc8(a, q10, q11);
        acc8(a, q20, q21);
        acc8(a, q30, q31);
    }
    for (; k < cnt; k++) {
        const uint2* p0 = src + ((unsigned)lst[k] << 6) + lx;
        acc8(a, p0[0], p0[1]);
    }
    float4 o0 = make_float4(a[0] * se, a[1] * se, a[2] * se, a[3] * se);
    float4 o1 = make_float4(a[4] * se, a[5] * se, a[6] * se, a[7] * se);
    float* op = out + (size_t)e * DIM + lane * 8;
    *(float4*)(op)     = o0;
    *(float4*)(op + 4) = o1;
}

__global__ __launch_bounds__(256) void spmm_nodes_kernel(const uint2* __restrict__ src,
                                                         float* __restrict__ out) {
    int i    = blockIdx.x * 8 + (threadIdx.x >> 5);
    int lane = threadIdx.x & 31;
    int cnt = g_rcnt[i];
    const int* lst = &g_cols[i * CAP_R];
    const int lx = lane << 1;
    float a[8];
#pragma unroll
    for (int r = 0; r < 8; r++) a[r] = 0.0f;
    int k = 0;
    for (; k + 4 <= cnt; k += 4) {
        int4 l = *(const int4*)(lst + k);
        const uint2* p0 = src + ((unsigned)l.x << 6) + lx;
        const uint2* p1 = src + ((unsigned)l.y << 6) + lx;
        const uint2* p2 = src + ((unsigned)l.z << 6) + lx;
        const uint2* p3 = src + ((unsigned)l.w << 6) + lx;
        uint2 q00 = p0[0], q01 = p0[1];
        uint2 q10 = p1[0], q11 = p1[1];
        uint2 q20 = p2[0], q21 = p2[1];
        uint2 q30 = p3[0], q31 = p3[1];
        acc8(a, q00, q01);
        acc8(a, q10, q11);
        acc8(a, q20, q21);
        acc8(a, q30, q31);
    }
    for (; k < cnt; k++) {
        const uint2* p0 = src + ((unsigned)lst[k] << 6) + lx;
        acc8(a, p0[0], p0[1]);
    }
    float sv = g_invsv[i];
    float4 o0 = make_float4(a[0] * sv, a[1] * sv, a[2] * sv, a[3] * sv);
    float4 o1 = make_float4(a[4] * sv, a[5] * sv, a[6] * sv, a[7] * sv);
    float* op = out + (size_t)i * DIM + lane * 8;
    *(float4*)(op)     = o0;
    *(float4*)(op + 4) = o1;
}

// ---------------- tensor-core GEMM: ldmatrix + conflict-free smem -----------
__device__ __forceinline__ void mma_bf16(float* c, const unsigned* a, const unsigned* b) {
    asm volatile(
        "mma.sync.aligned.m16n8k16.row.col.f32.bf16.bf16.f32 "
        "{%0,%1,%2,%3}, {%4,%5,%6,%7}, {%8,%9}, {%0,%1,%2,%3};\n"
        : "+f"(c[0]), "+f"(c[1]), "+f"(c[2]), "+f"(c[3])
        : "r"(a[0]), "r"(a[1]), "r"(a[2]), "r"(a[3]), "r"(b[0]), "r"(b[1]));
}

__device__ __forceinline__ void ldsm_x4(unsigned* r, unsigned addr) {
    asm volatile("ldmatrix.sync.aligned.m8n8.x4.shared.b16 {%0,%1,%2,%3}, [%4];"
        : "=r"(r[0]), "=r"(r[1]), "=r"(r[2]), "=r"(r[3]) : "r"(addr));
}
__device__ __forceinline__ void ldsm_x4_t(unsigned& r0, unsigned& r1,
                                          unsigned& r2, unsigned& r3, unsigned addr) {
    asm volatile("ldmatrix.sync.aligned.m8n8.x4.trans.shared.b16 {%0,%1,%2,%3}, [%4];"
        : "=r"(r0), "=r"(r1), "=r"(r2), "=r"(r3) : "r"(addr));
}

// A smem: [m][kpair] pitch 20 u32 (ldmatrix rows conflict-free: 20m mod 32).
// B smem: k-major ushort [32][136] (272B pitch => ldmatrix rows 4k mod 32, clean).
template<bool RESID, bool GELU>
__global__ __launch_bounds__(256) void gemm_tc_kernel(
    const float* __restrict__ A,
    const __nv_bfloat16* __restrict__ Bh_g, const __nv_bfloat16* __restrict__ Bl_g,
    const float* __restrict__ bias, const float* __restrict__ resid,
    const float* __restrict__ gate, float* __restrict__ C,
    __nv_bfloat162* __restrict__ bfc, const float* __restrict__ rowscale,
    int M, int N, int K)
{
    __shared__ unsigned Ah[128][20];
    __shared__ unsigned Al[128][20];
    __shared__ unsigned short Bsh[32][136];
    __shared__ unsigned short Bsl[32][136];

    const int tid  = threadIdx.x;
    const int warp = tid >> 5;
    const int lane = tid & 31;
    const int l15  = lane & 15;
    const int lhi  = lane >> 4;
    const int grp  = lane >> 2;
    const int qd   = lane & 3;
    const int m0 = blockIdx.y * 128;
    const int n0 = blockIdx.x * 128;
    const int warpM = (warp >> 2) * 64;
    const int warpN = (warp & 3) * 32;

    const unsigned sAh = (unsigned)__cvta_generic_to_shared(&Ah[0][0]);
    const unsigned sAl = (unsigned)__cvta_generic_to_shared(&Al[0][0]);
    const unsigned sBh = (unsigned)__cvta_generic_to_shared(&Bsh[0][0]);
    const unsigned sBl = (unsigned)__cvta_generic_to_shared(&Bsl[0][0]);

    float acc[4][4][4];
#pragma unroll
    for (int mf = 0; mf < 4; mf++)
#pragma unroll
        for (int nf = 0; nf < 4; nf++)
#pragma unroll
            for (int r = 0; r < 4; r++) acc[mf][nf][r] = 0.0f;

    float4 ra[4];
    ushort4 rbh[4], rbl[4];
    const int a_m  = tid >> 3;            // 0..31 (+i*32)
    const int a_k4 = (tid & 7) * 4;       // k element base (0..28)
    const int b_k  = tid >> 5;            // 0..7 (+i*8)
    const int b_n4 = (tid & 31) * 4;      // n element base (0..124)

#pragma unroll
    for (int i = 0; i < 4; i++)
        ra[i] = *(const float4*)(A + (size_t)(m0 + a_m + i * 32) * K + a_k4);
#pragma unroll
    for (int i = 0; i < 4; i++) {
        size_t off = (size_t)(b_k + i * 8) * N + n0 + b_n4;
        rbh[i] = *(const ushort4*)(Bh_g + off);
        rbl[i] = *(const ushort4*)(Bl_g + off);
    }

    const int ntiles = K / 32;
    for (int t = 0; t < ntiles; t++) {
        // A convert + STS.64 pair stores
#pragma unroll
        for (int i = 0; i < 4; i++) {
            float4 v = ra[i];
            __nv_bfloat162 h01 = __floats2bfloat162_rn(v.x, v.y);
            __nv_bfloat162 h23 = __floats2bfloat162_rn(v.z, v.w);
            float2 f01 = __bfloat1622float2(h01);
            float2 f23 = __bfloat1622float2(h23);
            __nv_bfloat162 l01 = __floats2bfloat162_rn(v.x - f01.x, v.y - f01.y);
            __nv_bfloat162 l23 = __floats2bfloat162_rn(v.z - f23.x, v.w - f23.y);
            int m = a_m + i * 32;
            uint2 hp = make_uint2(*(unsigned*)&h01, *(unsigned*)&h23);
            uint2 lp = make_uint2(*(unsigned*)&l01, *(unsigned*)&l23);
            *(uint2*)&Ah[m][a_k4 / 2] = hp;
            *(uint2*)&Al[m][a_k4 / 2] = lp;
        }
        // B k-major STS.64 stores (coalesced, ~2-way max)
#pragma unroll
        for (int i = 0; i < 4; i++) {
            *(ushort4*)&Bsh[b_k + i * 8][b_n4] = rbh[i];
            *(ushort4*)&Bsl[b_k + i * 8][b_n4] = rbl[i];
        }
        __syncthreads();

        if (t + 1 < ntiles) {
            int k0 = (t + 1) * 32;
#pragma unroll
            for (int i = 0; i < 4; i++)
                ra[i] = *(const float4*)(A + (size_t)(m0 + a_m + i * 32) * K + k0 + a_k4);
#pragma unroll
            for (int i = 0; i < 4; i++) {
                size_t off = (size_t)(k0 + b_k + i * 8) * N + n0 + b_n4;
                rbh[i] = *(const ushort4*)(Bh_g + off);
                rbl[i] = *(const ushort4*)(Bl_g + off);
            }
        }

#pragma unroll
        for (int ks = 0; ks < 2; ks++) {
            unsigned afh[4][4], afl[4][4], bfh[4][2], bfl[4][2];
            // A fragments: ldmatrix.x4 (non-trans)
#pragma unroll
            for (int mf = 0; mf < 4; mf++) {
                unsigned rowoff = (unsigned)(warpM + mf * 16 + l15) * 80u
                                + (unsigned)(ks * 32 + lhi * 16);
                ldsm_x4(afh[mf], sAh + rowoff);
                ldsm_x4(afl[mf], sAl + rowoff);
            }
            // B fragments: ldmatrix.x4.trans, 2 n-frags per issue
#pragma unroll
            for (int p = 0; p < 2; p++) {
                unsigned boff = (unsigned)(ks * 16 + l15) * 272u
                              + (unsigned)(warpN + p * 16 + lhi * 8) * 2u;
                ldsm_x4_t(bfh[2*p][0], bfh[2*p][1], bfh[2*p+1][0], bfh[2*p+1][1], sBh + boff);
                ldsm_x4_t(bfl[2*p][0], bfl[2*p][1], bfl[2*p+1][0], bfl[2*p+1][1], sBl + boff);
            }
            // hi*hi + lo*hi
#pragma unroll
            for (int mf = 0; mf < 4; mf++)
#pragma unroll
                for (int nf = 0; nf < 4; nf++) {
                    mma_bf16(acc[mf][nf], afh[mf], bfh[nf]);
                    mma_bf16(acc[mf][nf], afl[mf], bfh[nf]);
                }
            // hi*lo
#pragma unroll
            for (int mf = 0; mf < 4; mf++)
#pragma unroll
                for (int nf = 0; nf < 4; nf++)
                    mma_bf16(acc[mf][nf], afh[mf], bfl[nf]);
        }
        __syncthreads();
    }

    float alpha = 1.0f;
    if (!GELU && gate != nullptr) alpha = tanhf(gate[0]);

#pragma unroll
    for (int mf = 0; mf < 4; mf++) {
#pragma unroll
        for (int nf = 0; nf < 4; nf++) {
            int col = n0 + warpN + nf * 8 + 2 * qd;
            float bv0 = bias[col], bv1 = bias[col + 1];
            int r0 = m0 + warpM + mf * 16 + grp;
#pragma unroll
            for (int half = 0; half < 2; half++) {
                int row = r0 + half * 8;
                float v0 = acc[mf][nf][half * 2 + 0] + bv0;
                float v1 = acc[mf][nf][half * 2 + 1] + bv1;
                if (GELU) {
                    v0 = 0.5f * v0 * (1.0f + erff(v0 * 0.7071067811865476f));
                    v1 = 0.5f * v1 * (1.0f + erff(v1 * 0.7071067811865476f));
                } else {
                    v0 *= alpha; v1 *= alpha;
                }
                size_t base = (size_t)row * N + col;
                if (RESID) {
                    float2 r = *(const float2*)(resid + base);
                    v0 += r.x; v1 += r.y;
                }
                *(float2*)(C + base) = make_float2(v0, v1);
                if (bfc) {
                    float s = rowscale ? rowscale[row] : 1.0f;
                    bfc[base >> 1] = __floats2bfloat162_rn(v0 * s, v1 * s);
                }
            }
        }
    }
}

// ---------------- fused double LayerNorm -------------------------------------
__device__ __forceinline__ float block_sum_256(float v, float* sm) {
#pragma unroll
    for (int o = 16; o > 0; o >>= 1) v += __shfl_xor_sync(0xffffffffu, v, o);
    int w = threadIdx.x >> 5, lane = threadIdx.x & 31;
    if (lane == 0) sm[w] = v;
    __syncthreads();
    if (w == 0) {
        float s = (lane < 8) ? sm[lane] : 0.0f;
#pragma unroll
        for (int o = 4; o > 0; o >>= 1) s += __shfl_xor_sync(0xffffffffu, s, o);
        if (lane == 0) sm[0] = s;
    }
    __syncthreads();
    float r = sm[0];
    __syncthreads();
    return r;
}

__global__ __launch_bounds__(DIM) void ln_double_kernel(
    const float* __restrict__ g1, const float* __restrict__ b1,
    const float* __restrict__ g2, const float* __restrict__ b2)
{
    __shared__ float sm[8];
    int r = blockIdx.x, t = threadIdx.x;
    float v = g_u[(size_t)r * DIM + t];
    float mean = block_sum_256(v, sm) * (1.0f / DIM);
    float d = v - mean;
    float var = block_sum_256(d * d, sm) * (1.0f / DIM);
    float y = d * rsqrtf(var + LN_EPS) * g1[t] + b1[t];
    {
        float sv = g_invsv[r];
        float y_hi = __shfl_xor_sync(0xffffffffu, y, 1);
        if ((t & 1) == 0)
            g_x0lbf[((size_t)r * DIM + t) >> 1] = __floats2bfloat162_rn(y * sv, y_hi * sv);
    }
    float m2 = block_sum_256(y, sm) * (1.0f / DIM);
    float d2 = y - m2;
    float v2 = block_sum_256(d2 * d2, sm) * (1.0f / DIM);
    g_x0g[(size_t)r * DIM + t] = d2 * rsqrtf(v2 + LN_EPS) * g2[t] + b2[t];
}

// ---------------- driver -----------------------------------------------------
extern "C" void kernel_launch(void* const* d_in, const int* in_sizes, int n_in,
                              void* d_out, int out_size) {
    const float* x0   = (const float*)d_in[0];
    const float* x1   = (const float*)d_in[1];
    const float* H    = (const float*)d_in[2];
    const float* Wn   = (const float*)d_in[3];
    const float* bn   = (const float*)d_in[4];
    const float* We   = (const float*)d_in[5];
    const float* be   = (const float*)d_in[6];
    const float* Wr   = (const float*)d_in[7];
    const float* br   = (const float*)d_in[8];
    const float* W1   = (const float*)d_in[9];
    const float* b1   = (const float*)d_in[10];
    const float* W2   = (const float*)d_in[11];
    const float* b2   = (const float*)d_in[12];
    const float* ln1g = (const float*)d_in[13];
    const float* ln1b = (const float*)d_in[14];
    const float* ln2g = (const float*)d_in[15];
    const float* ln2b = (const float*)d_in[16];
    const float* gl   = (const float*)d_in[17];
    const float* gr   = (const float*)d_in[18];

    float* out_x0 = (float*)d_out;
    float* out_x1 = (float*)d_out + (size_t)NN * DIM;

    float *p_tmpE, *p_x1a, *p_msg, *p_u, *p_x0g, *p_ret, *p_h, *p_invse;
    __nv_bfloat162 *p_x0bf, *p_x1abf, *p_x0lbf;
    __nv_bfloat16 *p_wh, *p_wl;
    cudaGetSymbolAddress((void**)&p_tmpE, g_tmpE);
    cudaGetSymbolAddress((void**)&p_x1a,  g_x1a);
    cudaGetSymbolAddress((void**)&p_msg,  g_msg);
    cudaGetSymbolAddress((void**)&p_u,    g_u);
    cudaGetSymbolAddress((void**)&p_x0g,  g_x0g);
    cudaGetSymbolAddress((void**)&p_ret,  g_ret);
    cudaGetSymbolAddress((void**)&p_h,    g_h);
    cudaGetSymbolAddress((void**)&p_invse, g_invse);
    cudaGetSymbolAddress((void**)&p_x0bf,  g_x0bf);
    cudaGetSymbolAddress((void**)&p_x1abf, g_x1abf);
    cudaGetSymbolAddress((void**)&p_x0lbf, g_x0lbf);
    cudaGetSymbolAddress((void**)&p_wh, g_wh);
    cudaGetSymbolAddress((void**)&p_wl, g_wl);

    // 1) sparse build + weight prepack (fused, DRAM-bound)
    build_csr_kernel<<<NN / 8, 256>>>(H, We, Wn, Wr, W1, W2);
    // 2) scatter + x0->bf16(*invsv)
    scatter_cvt_kernel<<<(NN * CAP_R) / 256, 256>>>(x0);
    // 3) tmpE = H_norm^T @ x0   (publishes invse)
    spmm_edges_kernel<<<EE / 8, 256>>>((const uint2*)p_x0bf, p_tmpE);
    // 4) x1a = x1 + tmpE @ We + be   <-- ncu profiled slot this round
    gemm_tc_kernel<true, false><<<dim3(DIM / 128, EE / 128), 256>>>(
        p_tmpE, p_wh + OFF_WE, p_wl + OFF_WE, be, x1, nullptr, p_x1a, p_x1abf, p_invse,
        EE, DIM, DIM);
    // 5) msg = H_norm @ x1a
    spmm_nodes_kernel<<<NN / 8, 256>>>((const uint2*)p_x1abf, p_msg);
    // 6) u = x0 + tanh(gl) * (msg @ Wn + bn)
    gemm_tc_kernel<true, false><<<dim3(DIM / 128, NN / 128), 256>>>(
        p_msg, p_wh + OFF_WN, p_wl + OFF_WN, bn, x0, gl, p_u, nullptr, nullptr,
        NN, DIM, DIM);
    // 7) LN1 (bf16*invsv out) + LN2 (fp32 out)
    ln_double_kernel<<<NN, DIM>>>(ln1g, ln1b, ln2g, ln2b);
    // 8) ret = H_norm^T @ x0_local
    spmm_edges_kernel<<<EE / 8, 256>>>((const uint2*)p_x0lbf, p_ret);
    // 9) x1_out = x1a + tanh(gr) * (ret @ Wr + br)
    gemm_tc_kernel<true, false><<<dim3(DIM / 128, EE / 128), 256>>>(
        p_ret, p_wh + OFF_WR, p_wl + OFF_WR, br, p_x1a, gr, out_x1, nullptr, nullptr,
        EE, DIM, DIM);
    // 10) h = gelu(x0_global @ W1 + b1)
    gemm_tc_kernel<false, true><<<dim3((2 * DIM) / 128, NN / 128), 256>>>(
        p_x0g, p_wh + OFF_W1, p_wl + OFF_W1, b1, nullptr, nullptr, p_h, nullptr, nullptr,
        NN, 2 * DIM, DIM);
    // 11) x0_out = x0_global + h @ W2 + b2
    gemm_tc_kernel<true, false><<<dim3(DIM / 128, NN / 128), 256>>>(
        p_h, p_wh + OFF_W2, p_wl + OFF_W2, b2, p_x0g, nullptr, out_x0, nullptr, nullptr,
        NN, DIM, 2 * DIM);

    (void)in_sizes; (void)n_in; (void)out_size;
}

// round 8
// speedup vs baseline: 1.8456x; 1.0656x over previous
#include <cuda_runtime.h>
#include <cuda_bf16.h>
#include <math.h>

// Problem constants
#define NN   16384
#define EE   8192
#define DIM  256
#define CAP_R 128
#define CAP_C 192
#define LN_EPS 1e-5f

// Weight-plane offsets (elements) inside g_wh / g_wl
#define OFF_WE 0
#define OFF_WN 65536
#define OFF_WR 131072
#define OFF_W1 196608
#define OFF_W2 327680
#define W_TOTAL 458752

// ---------------- static device scratch (no allocations allowed) ------------
__device__ int   g_cols[NN * CAP_R];
__device__ int   g_rows[EE * CAP_C];
__device__ int   g_rcnt[NN];
__device__ int   g_ccnt[EE];
__device__ float g_invsv[NN];
__device__ float g_invse[EE];

__device__ float g_tmpE[EE * DIM];
__device__ float g_x1a [EE * DIM];
__device__ float g_msg [NN * DIM];
__device__ float g_u   [NN * DIM];
__device__ float g_x0g [NN * DIM];
__device__ float g_ret [EE * DIM];
__device__ float g_h   [NN * 2 * DIM];

// bf16 gather sources for the SpMMs (pre-scaled by their row norm factors)
__device__ __nv_bfloat162 g_x0bf [NN * DIM / 2];
__device__ __nv_bfloat162 g_x1abf[EE * DIM / 2];
__device__ __nv_bfloat162 g_x0lbf[NN * DIM / 2];

// pre-split bf16 hi/lo weight planes
__device__ __nv_bfloat16 g_wh[W_TOTAL];
__device__ __nv_bfloat16 g_wl[W_TOTAL];

// ---------------- sparse build + weight prepack (fused; DRAM-bound) ---------
__global__ __launch_bounds__(256) void build_csr_kernel(
    const float* __restrict__ H,
    const float* __restrict__ We, const float* __restrict__ Wn,
    const float* __restrict__ Wr, const float* __restrict__ W1,
    const float* __restrict__ W2)
{
    int gtid = blockIdx.x * blockDim.x + threadIdx.x;
    if (gtid < EE) g_ccnt[gtid] = 0;
    if (gtid < W_TOTAL) {
        const float* src; int off;
        if      (gtid < OFF_WN) { src = We; off = OFF_WE; }
        else if (gtid < OFF_WR) { src = Wn; off = OFF_WN; }
        else if (gtid < OFF_W1) { src = Wr; off = OFF_WR; }
        else if (gtid < OFF_W2) { src = W1; off = OFF_W1; }
        else                    { src = W2; off = OFF_W2; }
        float v = src[gtid - off];
        __nv_bfloat16 h = __float2bfloat16_rn(v);
        g_wh[gtid] = h;
        g_wl[gtid] = __float2bfloat16_rn(v - __bfloat162float(h));
    }

    int warp = gtid >> 5;
    int lane = threadIdx.x & 31;
    if (warp >= NN) return;
    const float* row = H + (size_t)warp * EE;
    int base = 0;
    for (int it = 0; it < EE / 128; it++) {
        float4 v4 = *(const float4*)(row + it * 128 + lane * 4);
        float v[4] = {v4.x, v4.y, v4.z, v4.w};
#pragma unroll
        for (int j = 0; j < 4; j++) {
            unsigned m = __ballot_sync(0xffffffffu, v[j] != 0.0f);
            if (v[j] != 0.0f) {
                int pos = base + __popc(m & ((1u << lane) - 1u));
                if (pos < CAP_R) g_cols[warp * CAP_R + pos] = it * 128 + lane * 4 + j;
            }
            base += __popc(m);
        }
    }
    if (lane == 0) {
        g_rcnt[warp]  = min(base, CAP_R);
        g_invsv[warp] = rsqrtf(fmaxf((float)base, 1.0f));
    }
}

// Fused: CSR->CSC scatter + x0 -> bf16 (pre-scaled by invsv[row]).
__global__ void scatter_cvt_kernel(const float* __restrict__ x0) {
    int tid = blockIdx.x * blockDim.x + threadIdx.x;
    int row = tid >> 7;
    float2 p = *(const float2*)(x0 + (size_t)tid * 2);
    float s = g_invsv[row];
    g_x0bf[tid] = __floats2bfloat162_rn(p.x * s, p.y * s);

    int k = tid & (CAP_R - 1);
    if (k < g_rcnt[row]) {
        int col = g_cols[row * CAP_R + k];
        int p2 = atomicAdd(&g_ccnt[col], 1);
        if (p2 < CAP_C) g_rows[col * CAP_C + p2] = row;
    }
}

// ---------------- SpMM gathers: warp-per-row, LDG.64 (bf16x4) ---------------
__device__ __forceinline__ void acc8(float* a, uint2 q0, uint2 q1) {
    float2 f;
    f = __bfloat1622float2(*(__nv_bfloat162*)&q0.x); a[0] += f.x; a[1] += f.y;
    f = __bfloat1622float2(*(__nv_bfloat162*)&q0.y); a[2] += f.x; a[3] += f.y;
    f = __bfloat1622float2(*(__nv_bfloat162*)&q1.x); a[4] += f.x; a[5] += f.y;
    f = __bfloat1622float2(*(__nv_bfloat162*)&q1.y); a[6] += f.x; a[7] += f.y;
}

__global__ __launch_bounds__(256) void spmm_edges_kernel(const uint2* __restrict__ src,
                                                         float* __restrict__ out) {
    int e    = blockIdx.x * 8 + (threadIdx.x >> 5);
    int lane = threadIdx.x & 31;
    int craw = g_ccnt[e];
    float se = rsqrtf(fmaxf((float)craw, 1.0f));
    if (lane == 0) g_invse[e] = se;
    int cnt = min(craw, CAP_C);
    const int* lst = &g_rows[e * CAP_C];
    const int lx = lane << 1;
    float a[8];
#pragma unroll
    for (int r = 0; r < 8; r++) a[r] = 0.0f;
    int k = 0;
    for (; k + 4 <= cnt; k += 4) {
        int4 l = *(const int4*)(lst + k);
        const uint2* p0 = src + ((unsigned)l.x << 6) + lx;
        const uint2* p1 = src + ((unsigned)l.y << 6) + lx;
        const uint2* p2 = src + ((unsigned)l.z << 6) + lx;
        const uint2* p3 = src + ((unsigned)l.w << 6) + lx;
        uint2 q00 = p0[0], q01 = p0[1];
        uint2 q10 = p1[0], q11 = p1[1];
        uint2 q20 = p2[0], q21 = p2[1];
        uint2 q30 = p3[0], q31 = p3[1];
        acc8(a, q00, q01);
        acc8(a, q10, q11);
        acc8(a, q20, q21);
        acc8(a, q30, q31);
    }
    for (; k < cnt; k++) {
        const uint2* p0 = src + ((unsigned)lst[k] << 6) + lx;
        acc8(a, p0[0], p0[1]);
    }
    float4 o0 = make_float4(a[0] * se, a[1] * se, a[2] * se, a[3] * se);
    float4 o1 = make_float4(a[4] * se, a[5] * se, a[6] * se, a[7] * se);
    float* op = out + (size_t)e * DIM + lane * 8;
    *(float4*)(op)     = o0;
    *(float4*)(op + 4) = o1;
}

__global__ __launch_bounds__(256) void spmm_nodes_kernel(const uint2* __restrict__ src,
                                                         float* __restrict__ out) {
    int i    = blockIdx.x * 8 + (threadIdx.x >> 5);
    int lane = threadIdx.x & 31;
    int cnt = g_rcnt[i];
    const int* lst = &g_cols[i * CAP_R];
    const int lx = lane << 1;
    float a[8];
#pragma unroll
    for (int r = 0; r < 8; r++) a[r] = 0.0f;
    int k = 0;
    for (; k + 4 <= cnt; k += 4) {
        int4 l = *(const int4*)(lst + k);
        const uint2* p0 = src + ((unsigned)l.x << 6) + lx;
        const uint2* p1 = src + ((unsigned)l.y << 6) + lx;
        const uint2* p2 = src + ((unsigned)l.z << 6) + lx;
        const uint2* p3 = src + ((unsigned)l.w << 6) + lx;
        uint2 q00 = p0[0], q01 = p0[1];
        uint2 q10 = p1[0], q11 = p1[1];
        uint2 q20 = p2[0], q21 = p2[1];
        uint2 q30 = p3[0], q31 = p3[1];
        acc8(a, q00, q01);
        acc8(a, q10, q11);
        acc8(a, q20, q21);
        acc8(a, q30, q31);
    }
    for (; k < cnt; k++) {
        const uint2* p0 = src + ((unsigned)lst[k] << 6) + lx;
        acc8(a, p0[0], p0[1]);
    }
    float sv = g_invsv[i];
    float4 o0 = make_float4(a[0] * sv, a[1] * sv, a[2] * sv, a[3] * sv);
    float4 o1 = make_float4(a[4] * sv, a[5] * sv, a[6] * sv, a[7] * sv);
    float* op = out + (size_t)i * DIM + lane * 8;
    *(float4*)(op)     = o0;
    *(float4*)(op + 4) = o1;
}

// ---------------- tensor-core GEMM: 64x128 CTA tile, 2 CTAs/SM --------------
__device__ __forceinline__ void mma_bf16(float* c, const unsigned* a, const unsigned* b) {
    asm volatile(
        "mma.sync.aligned.m16n8k16.row.col.f32.bf16.bf16.f32 "
        "{%0,%1,%2,%3}, {%4,%5,%6,%7}, {%8,%9}, {%0,%1,%2,%3};\n"
        : "+f"(c[0]), "+f"(c[1]), "+f"(c[2]), "+f"(c[3])
        : "r"(a[0]), "r"(a[1]), "r"(a[2]), "r"(a[3]), "r"(b[0]), "r"(b[1]));
}

__device__ __forceinline__ void ldsm_x4(unsigned* r, unsigned addr) {
    asm volatile("ldmatrix.sync.aligned.m8n8.x4.shared.b16 {%0,%1,%2,%3}, [%4];"
        : "=r"(r[0]), "=r"(r[1]), "=r"(r[2]), "=r"(r[3]) : "r"(addr));
}
__device__ __forceinline__ void ldsm_x4_t(unsigned& r0, unsigned& r1,
                                          unsigned& r2, unsigned& r3, unsigned addr) {
    asm volatile("ldmatrix.sync.aligned.m8n8.x4.trans.shared.b16 {%0,%1,%2,%3}, [%4];"
        : "=r"(r0), "=r"(r1), "=r"(r2), "=r"(r3) : "r"(addr));
}

// CTA tile 64(M) x 128(N), k-tile 32. 8 warps in 2(M) x 4(N); warp tile 32x32.
// A smem: [m][kpair] pitch 20 u32. B smem: k-major ushort [32][136].
template<bool RESID, bool GELU>
__global__ __launch_bounds__(256, 2) void gemm_tc_kernel(
    const float* __restrict__ A,
    const __nv_bfloat16* __restrict__ Bh_g, const __nv_bfloat16* __restrict__ Bl_g,
    const float* __restrict__ bias, const float* __restrict__ resid,
    const float* __restrict__ gate, float* __restrict__ C,
    __nv_bfloat162* __restrict__ bfc, const float* __restrict__ rowscale,
    int M, int N, int K)
{
    __shared__ unsigned Ah[64][20];
    __shared__ unsigned Al[64][20];
    __shared__ unsigned short Bsh[32][136];
    __shared__ unsigned short Bsl[32][136];

    const int tid  = threadIdx.x;
    const int warp = tid >> 5;
    const int lane = tid & 31;
    const int l15  = lane & 15;
    const int lhi  = lane >> 4;
    const int grp  = lane >> 2;
    const int qd   = lane & 3;
    const int m0 = blockIdx.y * 64;
    const int n0 = blockIdx.x * 128;
    const int warpM = (warp >> 2) * 32;   // 2 warp rows
    const int warpN = (warp & 3) * 32;    // 4 warp cols

    const unsigned sAh = (unsigned)__cvta_generic_to_shared(&Ah[0][0]);
    const unsigned sAl = (unsigned)__cvta_generic_to_shared(&Al[0][0]);
    const unsigned sBh = (unsigned)__cvta_generic_to_shared(&Bsh[0][0]);
    const unsigned sBl = (unsigned)__cvta_generic_to_shared(&Bsl[0][0]);

    float acc[2][4][4];
#pragma unroll
    for (int mf = 0; mf < 2; mf++)
#pragma unroll
        for (int nf = 0; nf < 4; nf++)
#pragma unroll
            for (int r = 0; r < 4; r++) acc[mf][nf][r] = 0.0f;

    // A tile: 64 rows x 32 k fp32 = 2048 floats; 256 thr x 8 floats (2 float4)
    float4 ra[2];
    ushort4 rbh[4], rbl[4];
    const int a_m  = tid >> 2;            // 0..63
    const int a_k8 = (tid & 3) * 8;       // 0,8,16,24
    const int b_k  = tid >> 5;            // 0..7 (+i*8)
    const int b_n4 = (tid & 31) * 4;      // 0..124

    ra[0] = *(const float4*)(A + (size_t)(m0 + a_m) * K + a_k8);
    ra[1] = *(const float4*)(A + (size_t)(m0 + a_m) * K + a_k8 + 4);
#pragma unroll
    for (int i = 0; i < 4; i++) {
        size_t off = (size_t)(b_k + i * 8) * N + n0 + b_n4;
        rbh[i] = *(const ushort4*)(Bh_g + off);
        rbl[i] = *(const ushort4*)(Bl_g + off);
    }

    const int ntiles = K / 32;
    for (int t = 0; t < ntiles; t++) {
        // A convert + STS.64 pair stores
#pragma unroll
        for (int i = 0; i < 2; i++) {
            float4 v = ra[i];
            __nv_bfloat162 h01 = __floats2bfloat162_rn(v.x, v.y);
            __nv_bfloat162 h23 = __floats2bfloat162_rn(v.z, v.w);
            float2 f01 = __bfloat1622float2(h01);
            float2 f23 = __bfloat1622float2(h23);
            __nv_bfloat162 l01 = __floats2bfloat162_rn(v.x - f01.x, v.y - f01.y);
            __nv_bfloat162 l23 = __floats2bfloat162_rn(v.z - f23.x, v.w - f23.y);
            uint2 hp = make_uint2(*(unsigned*)&h01, *(unsigned*)&h23);
            uint2 lp = make_uint2(*(unsigned*)&l01, *(unsigned*)&l23);
            *(uint2*)&Ah[a_m][a_k8 / 2 + i * 2] = hp;
            *(uint2*)&Al[a_m][a_k8 / 2 + i * 2] = lp;
        }
        // B k-major STS.64 stores
#pragma unroll
        for (int i = 0; i < 4; i++) {
            *(ushort4*)&Bsh[b_k + i * 8][b_n4] = rbh[i];
            *(ushort4*)&Bsl[b_k + i * 8][b_n4] = rbl[i];
        }
        __syncthreads();

        if (t + 1 < ntiles) {
            int k0 = (t + 1) * 32;
            ra[0] = *(const float4*)(A + (size_t)(m0 + a_m) * K + k0 + a_k8);
            ra[1] = *(const float4*)(A + (size_t)(m0 + a_m) * K + k0 + a_k8 + 4);
#pragma unroll
            for (int i = 0; i < 4; i++) {
                size_t off = (size_t)(k0 + b_k + i * 8) * N + n0 + b_n4;
                rbh[i] = *(const ushort4*)(Bh_g + off);
                rbl[i] = *(const ushort4*)(Bl_g + off);
            }
        }

#pragma unroll
        for (int ks = 0; ks < 2; ks++) {
            unsigned afh[2][4], afl[2][4], bfh[4][2], bfl[4][2];
#pragma unroll
            for (int mf = 0; mf < 2; mf++) {
                unsigned rowoff = (unsigned)(warpM + mf * 16 + l15) * 80u
                                + (unsigned)(ks * 32 + lhi * 16);
                ldsm_x4(afh[mf], sAh + rowoff);
                ldsm_x4(afl[mf], sAl + rowoff);
            }
#pragma unroll
            for (int p = 0; p < 2; p++) {
                unsigned boff = (unsigned)(ks * 16 + l15) * 272u
                              + (unsigned)(warpN + p * 16 + lhi * 8) * 2u;
                ldsm_x4_t(bfh[2*p][0], bfh[2*p][1], bfh[2*p+1][0], bfh[2*p+1][1], sBh + boff);
                ldsm_x4_t(bfl[2*p][0], bfl[2*p][1], bfl[2*p+1][0], bfl[2*p+1][1], sBl + boff);
            }
#pragma unroll
            for (int mf = 0; mf < 2; mf++)
#pragma unroll
                for (int nf = 0; nf < 4; nf++) {
                    mma_bf16(acc[mf][nf], afh[mf], bfh[nf]);
                    mma_bf16(acc[mf][nf], afl[mf], bfh[nf]);
                    mma_bf16(acc[mf][nf], afh[mf], bfl[nf]);
                }
        }
        __syncthreads();
    }

    float alpha = 1.0f;
    if (!GELU && gate != nullptr) alpha = tanhf(gate[0]);

#pragma unroll
    for (int mf = 0; mf < 2; mf++) {
#pragma unroll
        for (int nf = 0; nf < 4; nf++) {
            int col = n0 + warpN + nf * 8 + 2 * qd;
            float bv0 = bias[col], bv1 = bias[col + 1];
            int r0 = m0 + warpM + mf * 16 + grp;
#pragma unroll
            for (int half = 0; half < 2; half++) {
                int row = r0 + half * 8;
                float v0 = acc[mf][nf][half * 2 + 0] + bv0;
                float v1 = acc[mf][nf][half * 2 + 1] + bv1;
                if (GELU) {
                    v0 = 0.5f * v0 * (1.0f + erff(v0 * 0.7071067811865476f));
                    v1 = 0.5f * v1 * (1.0f + erff(v1 * 0.7071067811865476f));
                } else {
                    v0 *= alpha; v1 *= alpha;
                }
                size_t base = (size_t)row * N + col;
                if (RESID) {
                    float2 r = *(const float2*)(resid + base);
                    v0 += r.x; v1 += r.y;
                }
                *(float2*)(C + base) = make_float2(v0, v1);
                if (bfc) {
                    float s = rowscale ? rowscale[row] : 1.0f;
                    bfc[base >> 1] = __floats2bfloat162_rn(v0 * s, v1 * s);
                }
            }
        }
    }
}

// ---------------- fused double LayerNorm -------------------------------------
__device__ __forceinline__ float block_sum_256(float v, float* sm) {
#pragma unroll
    for (int o = 16; o > 0; o >>= 1) v += __shfl_xor_sync(0xffffffffu, v, o);
    int w = threadIdx.x >> 5, lane = threadIdx.x & 31;
    if (lane == 0) sm[w] = v;
    __syncthreads();
    if (w == 0) {
        float s = (lane < 8) ? sm[lane] : 0.0f;
#pragma unroll
        for (int o = 4; o > 0; o >>= 1) s += __shfl_xor_sync(0xffffffffu, s, o);
        if (lane == 0) sm[0] = s;
    }
    __syncthreads();
    float r = sm[0];
    __syncthreads();
    return r;
}

__global__ __launch_bounds__(DIM) void ln_double_kernel(
    const float* __restrict__ g1, const float* __restrict__ b1,
    const float* __restrict__ g2, const float* __restrict__ b2)
{
    __shared__ float sm[8];
    int r = blockIdx.x, t = threadIdx.x;
    float v = g_u[(size_t)r * DIM + t];
    float mean = block_sum_256(v, sm) * (1.0f / DIM);
    float d = v - mean;
    float var = block_sum_256(d * d, sm) * (1.0f / DIM);
    float y = d * rsqrtf(var + LN_EPS) * g1[t] + b1[t];
    {
        float sv = g_invsv[r];
        float y_hi = __shfl_xor_sync(0xffffffffu, y, 1);
        if ((t & 1) == 0)
            g_x0lbf[((size_t)r * DIM + t) >> 1] = __floats2bfloat162_rn(y * sv, y_hi * sv);
    }
    float m2 = block_sum_256(y, sm) * (1.0f / DIM);
    float d2 = y - m2;
    float v2 = block_sum_256(d2 * d2, sm) * (1.0f / DIM);
    g_x0g[(size_t)r * DIM + t] = d2 * rsqrtf(v2 + LN_EPS) * g2[t] + b2[t];
}

// ---------------- driver -----------------------------------------------------
extern "C" void kernel_launch(void* const* d_in, const int* in_sizes, int n_in,
                              void* d_out, int out_size) {
    const float* x0   = (const float*)d_in[0];
    const float* x1   = (const float*)d_in[1];
    const float* H    = (const float*)d_in[2];
    const float* Wn   = (const float*)d_in[3];
    const float* bn   = (const float*)d_in[4];
    const float* We   = (const float*)d_in[5];
    const float* be   = (const float*)d_in[6];
    const float* Wr   = (const float*)d_in[7];
    const float* br   = (const float*)d_in[8];
    const float* W1   = (const float*)d_in[9];
    const float* b1   = (const float*)d_in[10];
    const float* W2   = (const float*)d_in[11];
    const float* b2   = (const float*)d_in[12];
    const float* ln1g = (const float*)d_in[13];
    const float* ln1b = (const float*)d_in[14];
    const float* ln2g = (const float*)d_in[15];
    const float* ln2b = (const float*)d_in[16];
    const float* gl   = (const float*)d_in[17];
    const float* gr   = (const float*)d_in[18];

    float* out_x0 = (float*)d_out;
    float* out_x1 = (float*)d_out + (size_t)NN * DIM;

    float *p_tmpE, *p_x1a, *p_msg, *p_u, *p_x0g, *p_ret, *p_h, *p_invse;
    __nv_bfloat162 *p_x0bf, *p_x1abf, *p_x0lbf;
    __nv_bfloat16 *p_wh, *p_wl;
    cudaGetSymbolAddress((void**)&p_tmpE, g_tmpE);
    cudaGetSymbolAddress((void**)&p_x1a,  g_x1a);
    cudaGetSymbolAddress((void**)&p_msg,  g_msg);
    cudaGetSymbolAddress((void**)&p_u,    g_u);
    cudaGetSymbolAddress((void**)&p_x0g,  g_x0g);
    cudaGetSymbolAddress((void**)&p_ret,  g_ret);
    cudaGetSymbolAddress((void**)&p_h,    g_h);
    cudaGetSymbolAddress((void**)&p_invse, g_invse);
    cudaGetSymbolAddress((void**)&p_x0bf,  g_x0bf);
    cudaGetSymbolAddress((void**)&p_x1abf, g_x1abf);
    cudaGetSymbolAddress((void**)&p_x0lbf, g_x0lbf);
    cudaGetSymbolAddress((void**)&p_wh, g_wh);
    cudaGetSymbolAddress((void**)&p_wl, g_wl);

    // 1) sparse build + weight prepack (fused, DRAM-bound)
    build_csr_kernel<<<NN / 8, 256>>>(H, We, Wn, Wr, W1, W2);
    // 2) scatter + x0->bf16(*invsv)
    scatter_cvt_kernel<<<(NN * CAP_R) / 256, 256>>>(x0);
    // 3) tmpE = H_norm^T @ x0   (publishes invse)
    spmm_edges_kernel<<<EE / 8, 256>>>((const uint2*)p_x0bf, p_tmpE);
    // 4) x1a = x1 + tmpE @ We + be   <-- ncu profiled slot
    gemm_tc_kernel<true, false><<<dim3(DIM / 128, EE / 64), 256>>>(
        p_tmpE, p_wh + OFF_WE, p_wl + OFF_WE, be, x1, nullptr, p_x1a, p_x1abf, p_invse,
        EE, DIM, DIM);
    // 5) msg = H_norm @ x1a
    spmm_nodes_kernel<<<NN / 8, 256>>>((const uint2*)p_x1abf, p_msg);
    // 6) u = x0 + tanh(gl) * (msg @ Wn + bn)
    gemm_tc_kernel<true, false><<<dim3(DIM / 128, NN / 64), 256>>>(
        p_msg, p_wh + OFF_WN, p_wl + OFF_WN, bn, x0, gl, p_u, nullptr, nullptr,
        NN, DIM, DIM);
    // 7) LN1 (bf16*invsv out) + LN2 (fp32 out)
    ln_double_kernel<<<NN, DIM>>>(ln1g, ln1b, ln2g, ln2b);
    // 8) ret = H_norm^T @ x0_local
    spmm_edges_kernel<<<EE / 8, 256>>>((const uint2*)p_x0lbf, p_ret);
    // 9) x1_out = x1a + tanh(gr) * (ret @ Wr + br)
    gemm_tc_kernel<true, false><<<dim3(DIM / 128, EE / 64), 256>>>(
        p_ret, p_wh + OFF_WR, p_wl + OFF_WR, br, p_x1a, gr, out_x1, nullptr, nullptr,
        EE, DIM, DIM);
    // 10) h = gelu(x0_global @ W1 + b1)
    gemm_tc_kernel<false, true><<<dim3((2 * DIM) / 128, NN / 64), 256>>>(
        p_x0g, p_wh + OFF_W1, p_wl + OFF_W1, b1, nullptr, nullptr, p_h, nullptr, nullptr,
        NN, 2 * DIM, DIM);
    // 11) x0_out = x0_global + h @ W2 + b2
    gemm_tc_kernel<true, false><<<dim3(DIM / 128, NN / 64), 256>>>(
        p_h, p_wh + OFF_W2, p_wl + OFF_W2, b2, p_x0g, nullptr, out_x0, nullptr, nullptr,
        NN, DIM, 2 * DIM);

    (void)in_sizes; (void)n_in; (void)out_size;
}

// round 9
// speedup vs baseline: 1.9848x; 1.0754x over previous
#include <cuda_runtime.h>
#include <cuda_bf16.h>
#include <math.h>

// Problem constants
#define NN   16384
#define EE   8192
#define DIM  256
#define CAP_R 128
#define CAP_C 192
#define LN_EPS 1e-5f

// Weight-plane offsets (elements) inside g_wh / g_wl
#define OFF_WE 0
#define OFF_WN 65536
#define OFF_WR 131072
#define OFF_W1 196608
#define OFF_W2 327680
#define W_TOTAL 458752

// ---------------- static device scratch (no allocations allowed) ------------
__device__ int   g_cols[NN * CAP_R];
__device__ int   g_rows[EE * CAP_C];
__device__ int   g_rcnt[NN];
__device__ int   g_ccnt[EE];
__device__ float g_invsv[NN];
__device__ float g_invse[EE];

__device__ float g_x1a [EE * DIM];
__device__ float g_u   [NN * DIM];
__device__ float g_x0g [NN * DIM];

// bf16 gather sources for the SpMMs (pre-scaled by their row norm factors)
__device__ __nv_bfloat162 g_x0bf [NN * DIM / 2];
__device__ __nv_bfloat162 g_x1abf[EE * DIM / 2];
__device__ __nv_bfloat162 g_x0lbf[NN * DIM / 2];

// bf16 hi/lo planes for GEMM A operands (produced by upstream kernels)
__device__ __align__(16) __nv_bfloat16 g_tmpEh[EE * DIM], g_tmpEl[EE * DIM];
__device__ __align__(16) __nv_bfloat16 g_msgh [NN * DIM], g_msgl [NN * DIM];
__device__ __align__(16) __nv_bfloat16 g_reth [EE * DIM], g_retl [EE * DIM];
__device__ __align__(16) __nv_bfloat16 g_x0gh [NN * DIM], g_x0gl [NN * DIM];
__device__ __align__(16) __nv_bfloat16 g_hh [NN * 2 * DIM], g_hl [NN * 2 * DIM];

// pre-split bf16 hi/lo weight planes
__device__ __align__(16) __nv_bfloat16 g_wh[W_TOTAL];
__device__ __align__(16) __nv_bfloat16 g_wl[W_TOTAL];

// ---------------- sparse build + weight prepack (fused; DRAM-bound) ---------
__global__ __launch_bounds__(256) void build_csr_kernel(
    const float* __restrict__ H,
    const float* __restrict__ We, const float* __restrict__ Wn,
    const float* __restrict__ Wr, const float* __restrict__ W1,
    const float* __restrict__ W2)
{
    int gtid = blockIdx.x * blockDim.x + threadIdx.x;
    if (gtid < EE) g_ccnt[gtid] = 0;
    if (gtid < W_TOTAL) {
        const float* src; int off;
        if      (gtid < OFF_WN) { src = We; off = OFF_WE; }
        else if (gtid < OFF_WR) { src = Wn; off = OFF_WN; }
        else if (gtid < OFF_W1) { src = Wr; off = OFF_WR; }
        else if (gtid < OFF_W2) { src = W1; off = OFF_W1; }
        else                    { src = W2; off = OFF_W2; }
        float v = src[gtid - off];
        __nv_bfloat16 h = __float2bfloat16_rn(v);
        g_wh[gtid] = h;
        g_wl[gtid] = __float2bfloat16_rn(v - __bfloat162float(h));
    }

    int warp = gtid >> 5;
    int lane = threadIdx.x & 31;
    if (warp >= NN) return;
    const float* row = H + (size_t)warp * EE;
    int base = 0;
    for (int it = 0; it < EE / 128; it++) {
        float4 v4 = *(const float4*)(row + it * 128 + lane * 4);
        float v[4] = {v4.x, v4.y, v4.z, v4.w};
#pragma unroll
        for (int j = 0; j < 4; j++) {
            unsigned m = __ballot_sync(0xffffffffu, v[j] != 0.0f);
            if (v[j] != 0.0f) {
                int pos = base + __popc(m & ((1u << lane) - 1u));
                if (pos < CAP_R) g_cols[warp * CAP_R + pos] = it * 128 + lane * 4 + j;
            }
            base += __popc(m);
        }
    }
    if (lane == 0) {
        g_rcnt[warp]  = min(base, CAP_R);
        g_invsv[warp] = rsqrtf(fmaxf((float)base, 1.0f));
    }
}

// Fused: CSR->CSC scatter + x0 -> bf16 (pre-scaled by invsv[row]).
__global__ void scatter_cvt_kernel(const float* __restrict__ x0) {
    int tid = blockIdx.x * blockDim.x + threadIdx.x;
    int row = tid >> 7;
    float2 p = *(const float2*)(x0 + (size_t)tid * 2);
    float s = g_invsv[row];
    g_x0bf[tid] = __floats2bfloat162_rn(p.x * s, p.y * s);

    int k = tid & (CAP_R - 1);
    if (k < g_rcnt[row]) {
        int col = g_cols[row * CAP_R + k];
        int p2 = atomicAdd(&g_ccnt[col], 1);
        if (p2 < CAP_C) g_rows[col * CAP_C + p2] = row;
    }
}

// ---------------- SpMM gathers: warp-per-row, LDG.64, hi/lo plane output ----
__device__ __forceinline__ void acc8(float* a, uint2 q0, uint2 q1) {
    float2 f;
    f = __bfloat1622float2(*(__nv_bfloat162*)&q0.x); a[0] += f.x; a[1] += f.y;
    f = __bfloat1622float2(*(__nv_bfloat162*)&q0.y); a[2] += f.x; a[3] += f.y;
    f = __bfloat1622float2(*(__nv_bfloat162*)&q1.x); a[4] += f.x; a[5] += f.y;
    f = __bfloat1622float2(*(__nv_bfloat162*)&q1.y); a[6] += f.x; a[7] += f.y;
}

__device__ __forceinline__ void store_hilo8(const float* a, float s,
                                            __nv_bfloat16* outh, __nv_bfloat16* outl,
                                            size_t off) {
    unsigned hq[4], lq[4];
#pragma unroll
    for (int j = 0; j < 4; j++) {
        float x = a[2*j] * s, y = a[2*j+1] * s;
        __nv_bfloat162 h2 = __floats2bfloat162_rn(x, y);
        float2 hf = __bfloat1622float2(h2);
        __nv_bfloat162 l2 = __floats2bfloat162_rn(x - hf.x, y - hf.y);
        hq[j] = *(unsigned*)&h2;
        lq[j] = *(unsigned*)&l2;
    }
    *(uint4*)(outh + off) = make_uint4(hq[0], hq[1], hq[2], hq[3]);
    *(uint4*)(outl + off) = make_uint4(lq[0], lq[1], lq[2], lq[3]);
}

__global__ __launch_bounds__(256) void spmm_edges_kernel(const uint2* __restrict__ src,
                                                         __nv_bfloat16* __restrict__ outh,
                                                         __nv_bfloat16* __restrict__ outl) {
    int e    = blockIdx.x * 8 + (threadIdx.x >> 5);
    int lane = threadIdx.x & 31;
    int craw = g_ccnt[e];
    float se = rsqrtf(fmaxf((float)craw, 1.0f));
    if (lane == 0) g_invse[e] = se;
    int cnt = min(craw, CAP_C);
    const int* lst = &g_rows[e * CAP_C];
    const int lx = lane << 1;
    float a[8];
#pragma unroll
    for (int r = 0; r < 8; r++) a[r] = 0.0f;
    int k = 0;
    for (; k + 4 <= cnt; k += 4) {
        int4 l = *(const int4*)(lst + k);
        const uint2* p0 = src + ((unsigned)l.x << 6) + lx;
        const uint2* p1 = src + ((unsigned)l.y << 6) + lx;
        const uint2* p2 = src + ((unsigned)l.z << 6) + lx;
        const uint2* p3 = src + ((unsigned)l.w << 6) + lx;
        uint2 q00 = p0[0], q01 = p0[1];
        uint2 q10 = p1[0], q11 = p1[1];
        uint2 q20 = p2[0], q21 = p2[1];
        uint2 q30 = p3[0], q31 = p3[1];
        acc8(a, q00, q01);
        acc8(a, q10, q11);
        acc8(a, q20, q21);
        acc8(a, q30, q31);
    }
    for (; k < cnt; k++) {
        const uint2* p0 = src + ((unsigned)lst[k] << 6) + lx;
        acc8(a, p0[0], p0[1]);
    }
    store_hilo8(a, se, outh, outl, (size_t)e * DIM + lane * 8);
}

__global__ __launch_bounds__(256) void spmm_nodes_kernel(const uint2* __restrict__ src,
                                                         __nv_bfloat16* __restrict__ outh,
                                                         __nv_bfloat16* __restrict__ outl) {
    int i    = blockIdx.x * 8 + (threadIdx.x >> 5);
    int lane = threadIdx.x & 31;
    int cnt = g_rcnt[i];
    const int* lst = &g_cols[i * CAP_R];
    const int lx = lane << 1;
    float a[8];
#pragma unroll
    for (int r = 0; r < 8; r++) a[r] = 0.0f;
    int k = 0;
    for (; k + 4 <= cnt; k += 4) {
        int4 l = *(const int4*)(lst + k);
        const uint2* p0 = src + ((unsigned)l.x << 6) + lx;
        const uint2* p1 = src + ((unsigned)l.y << 6) + lx;
        const uint2* p2 = src + ((unsigned)l.z << 6) + lx;
        const uint2* p3 = src + ((unsigned)l.w << 6) + lx;
        uint2 q00 = p0[0], q01 = p0[1];
        uint2 q10 = p1[0], q11 = p1[1];
        uint2 q20 = p2[0], q21 = p2[1];
        uint2 q30 = p3[0], q31 = p3[1];
        acc8(a, q00, q01);
        acc8(a, q10, q11);
        acc8(a, q20, q21);
        acc8(a, q30, q31);
    }
    for (; k < cnt; k++) {
        const uint2* p0 = src + ((unsigned)lst[k] << 6) + lx;
        acc8(a, p0[0], p0[1]);
    }
    float sv = g_invsv[i];
    store_hilo8(a, sv, outh, outl, (size_t)i * DIM + lane * 8);
}

// ---------------- tensor-core GEMM: all-bf16, cp.async 3-stage pipeline -----
__device__ __forceinline__ void mma_bf16(float* c, const unsigned* a, const unsigned* b) {
    asm volatile(
        "mma.sync.aligned.m16n8k16.row.col.f32.bf16.bf16.f32 "
        "{%0,%1,%2,%3}, {%4,%5,%6,%7}, {%8,%9}, {%0,%1,%2,%3};\n"
        : "+f"(c[0]), "+f"(c[1]), "+f"(c[2]), "+f"(c[3])
        : "r"(a[0]), "r"(a[1]), "r"(a[2]), "r"(a[3]), "r"(b[0]), "r"(b[1]));
}
__device__ __forceinline__ void ldsm_x4(unsigned* r, unsigned addr) {
    asm volatile("ldmatrix.sync.aligned.m8n8.x4.shared.b16 {%0,%1,%2,%3}, [%4];"
        : "=r"(r[0]), "=r"(r[1]), "=r"(r[2]), "=r"(r[3]) : "r"(addr));
}
__device__ __forceinline__ void ldsm_x4_t(unsigned& r0, unsigned& r1,
                                          unsigned& r2, unsigned& r3, unsigned addr) {
    asm volatile("ldmatrix.sync.aligned.m8n8.x4.trans.shared.b16 {%0,%1,%2,%3}, [%4];"
        : "=r"(r0), "=r"(r1), "=r"(r2), "=r"(r3) : "r"(addr));
}
#define CP_ASYNC16(dst, src) \
    asm volatile("cp.async.ca.shared.global [%0], [%1], 16;" :: "r"(dst), "l"(src))
#define CP_COMMIT() asm volatile("cp.async.commit_group;")
#define CP_WAIT1()  asm volatile("cp.async.wait_group 1;" ::: "memory")

// CTA tile 64(M) x 128(N), KTILE=16, 3 smem stages.
// 8 warps 2(M) x 4(N); warp tile 32x32; 24 MMAs per warp per tile.
// A smem: ushort [64][24] (48B pitch, banks 12m mod 32 distinct).
// B smem: ushort [16][136] (272B pitch, banks 4k mod 32 distinct).
#define ASTG 3072   // 64*48 bytes per stage per plane
#define BSTG 4352   // 16*272 bytes per stage per plane

template<bool RESID, bool GELU>
__global__ __launch_bounds__(256, 2) void gemm_tc_kernel(
    const __nv_bfloat16* __restrict__ Ah_g, const __nv_bfloat16* __restrict__ Al_g,
    const __nv_bfloat16* __restrict__ Bh_g, const __nv_bfloat16* __restrict__ Bl_g,
    const float* __restrict__ bias, const float* __restrict__ resid,
    const float* __restrict__ gate, float* __restrict__ C,
    __nv_bfloat162* __restrict__ Ch, __nv_bfloat162* __restrict__ Cl,
    __nv_bfloat162* __restrict__ bfc, const float* __restrict__ rowscale,
    int M, int N, int K)
{
    __shared__ __align__(16) unsigned short Ahs[3][64][24];
    __shared__ __align__(16) unsigned short Als[3][64][24];
    __shared__ __align__(16) unsigned short Bhs[3][16][136];
    __shared__ __align__(16) unsigned short Bls[3][16][136];

    const int tid  = threadIdx.x;
    const int warp = tid >> 5;
    const int lane = tid & 31;
    const int l15  = lane & 15;
    const int lhi  = lane >> 4;
    const int grp  = lane >> 2;
    const int qd   = lane & 3;
    const int m0 = blockIdx.y * 64;
    const int n0 = blockIdx.x * 128;
    const int warpM = (warp >> 2) * 32;
    const int warpN = (warp & 3) * 32;

    const unsigned sAh = (unsigned)__cvta_generic_to_shared(&Ahs[0][0][0]);
    const unsigned sAl = (unsigned)__cvta_generic_to_shared(&Als[0][0][0]);
    const unsigned sBh = (unsigned)__cvta_generic_to_shared(&Bhs[0][0][0]);
    const unsigned sBl = (unsigned)__cvta_generic_to_shared(&Bls[0][0][0]);

    float acc[2][4][4];
#pragma unroll
    for (int mf = 0; mf < 2; mf++)
#pragma unroll
        for (int nf = 0; nf < 4; nf++)
#pragma unroll
            for (int r = 0; r < 4; r++) acc[mf][nf][r] = 0.0f;

    // cp.async thread mapping
    const int a_half = tid >> 7;             // 0: hi plane, 1: lo plane
    const int a_m    = (tid & 127) >> 1;     // 0..63
    const int a_c    = tid & 1;              // 16B chunk in 32B row
    const int b_k    = tid >> 4;             // 0..15
    const int b_c    = tid & 15;             // 16B chunk in 256B row
    const __nv_bfloat16* aplane = a_half ? Al_g : Ah_g;
    const unsigned aplane_s = a_half ? sAl : sAh;
    const size_t a_goff = (size_t)(m0 + a_m) * K + a_c * 8;
    const size_t b_goff = (size_t)b_k * N + n0 + b_c * 8;
    const unsigned a_soff = a_m * 48 + a_c * 16;
    const unsigned b_soff = b_k * 272 + b_c * 16;

    auto issue = [&](int s, int k0) {
        CP_ASYNC16(aplane_s + s * ASTG + a_soff, aplane + a_goff + k0);
        CP_ASYNC16(sBh + s * BSTG + b_soff, Bh_g + b_goff + (size_t)k0 * N);
        CP_ASYNC16(sBl + s * BSTG + b_soff, Bl_g + b_goff + (size_t)k0 * N);
    };

    const int ntiles = K / 16;
    issue(0, 0);  CP_COMMIT();
    issue(1, 16); CP_COMMIT();

#pragma unroll 1
    for (int t = 0; t < ntiles; t++) {
        CP_WAIT1();
        __syncthreads();
        if (t + 2 < ntiles) issue((t + 2) % 3, (t + 2) * 16);
        CP_COMMIT();

        const int s = t % 3;
        unsigned afh[2][4], afl[2][4], bfh[4][2], bfl[4][2];
#pragma unroll
        for (int mf = 0; mf < 2; mf++) {
            unsigned aoff = (unsigned)s * ASTG
                          + (unsigned)(warpM + mf * 16 + l15) * 48u + (unsigned)lhi * 16u;
            ldsm_x4(afh[mf], sAh + aoff);
            ldsm_x4(afl[mf], sAl + aoff);
        }
#pragma unroll
        for (int p = 0; p < 2; p++) {
            unsigned boff = (unsigned)s * BSTG + (unsigned)l15 * 272u
                          + (unsigned)(warpN + p * 16 + lhi * 8) * 2u;
            ldsm_x4_t(bfh[2*p][0], bfh[2*p][1], bfh[2*p+1][0], bfh[2*p+1][1], sBh + boff);
            ldsm_x4_t(bfl[2*p][0], bfl[2*p][1], bfl[2*p+1][0], bfl[2*p+1][1], sBl + boff);
        }
#pragma unroll
        for (int mf = 0; mf < 2; mf++)
#pragma unroll
            for (int nf = 0; nf < 4; nf++) {
                mma_bf16(acc[mf][nf], afh[mf], bfh[nf]);
                mma_bf16(acc[mf][nf], afl[mf], bfh[nf]);
                mma_bf16(acc[mf][nf], afh[mf], bfl[nf]);
            }
    }

    float alpha = 1.0f;
    if (!GELU && gate != nullptr) alpha = tanhf(gate[0]);

#pragma unroll
    for (int mf = 0; mf < 2; mf++) {
#pragma unroll
        for (int nf = 0; nf < 4; nf++) {
            int col = n0 + warpN + nf * 8 + 2 * qd;
            float bv0 = bias[col], bv1 = bias[col + 1];
            int r0 = m0 + warpM + mf * 16 + grp;
#pragma unroll
            for (int half = 0; half < 2; half++) {
                int row = r0 + half * 8;
                float v0 = acc[mf][nf][half * 2 + 0] + bv0;
                float v1 = acc[mf][nf][half * 2 + 1] + bv1;
                if (GELU) {
                    v0 = 0.5f * v0 * (1.0f + erff(v0 * 0.7071067811865476f));
                    v1 = 0.5f * v1 * (1.0f + erff(v1 * 0.7071067811865476f));
                } else {
                    v0 *= alpha; v1 *= alpha;
                }
                size_t base = (size_t)row * N + col;
                if (RESID) {
                    float2 r = *(const float2*)(resid + base);
                    v0 += r.x; v1 += r.y;
                }
                if (C) *(float2*)(C + base) = make_float2(v0, v1);
                if (Ch) {
                    __nv_bfloat162 h2 = __floats2bfloat162_rn(v0, v1);
                    float2 hf = __bfloat1622float2(h2);
                    __nv_bfloat162 l2 = __floats2bfloat162_rn(v0 - hf.x, v1 - hf.y);
                    Ch[base >> 1] = h2;
                    Cl[base >> 1] = l2;
                }
                if (bfc) {
                    float s = rowscale ? rowscale[row] : 1.0f;
                    bfc[base >> 1] = __floats2bfloat162_rn(v0 * s, v1 * s);
                }
            }
        }
    }
}

// ---------------- fused double LayerNorm -------------------------------------
__device__ __forceinline__ float block_sum_256(float v, float* sm) {
#pragma unroll
    for (int o = 16; o > 0; o >>= 1) v += __shfl_xor_sync(0xffffffffu, v, o);
    int w = threadIdx.x >> 5, lane = threadIdx.x & 31;
    if (lane == 0) sm[w] = v;
    __syncthreads();
    if (w == 0) {
        float s = (lane < 8) ? sm[lane] : 0.0f;
#pragma unroll
        for (int o = 4; o > 0; o >>= 1) s += __shfl_xor_sync(0xffffffffu, s, o);
        if (lane == 0) sm[0] = s;
    }
    __syncthreads();
    float r = sm[0];
    __syncthreads();
    return r;
}

__global__ __launch_bounds__(DIM) void ln_double_kernel(
    const float* __restrict__ g1, const float* __restrict__ b1,
    const float* __restrict__ g2, const float* __restrict__ b2)
{
    __shared__ float sm[8];
    int r = blockIdx.x, t = threadIdx.x;
    size_t idx = (size_t)r * DIM + t;
    float v = g_u[idx];
    float mean = block_sum_256(v, sm) * (1.0f / DIM);
    float d = v - mean;
    float var = block_sum_256(d * d, sm) * (1.0f / DIM);
    float y = d * rsqrtf(var + LN_EPS) * g1[t] + b1[t];
    {
        float sv = g_invsv[r];
        float y_hi = __shfl_xor_sync(0xffffffffu, y, 1);
        if ((t & 1) == 0)
            g_x0lbf[idx >> 1] = __floats2bfloat162_rn(y * sv, y_hi * sv);
    }
    float m2 = block_sum_256(y, sm) * (1.0f / DIM);
    float d2 = y - m2;
    float v2 = block_sum_256(d2 * d2, sm) * (1.0f / DIM);
    float z = d2 * rsqrtf(v2 + LN_EPS) * g2[t] + b2[t];
    g_x0g[idx] = z;
    {
        float z_n = __shfl_xor_sync(0xffffffffu, z, 1);
        if ((t & 1) == 0) {
            __nv_bfloat162 h2 = __floats2bfloat162_rn(z, z_n);
            float2 hf = __bfloat1622float2(h2);
            __nv_bfloat162 l2 = __floats2bfloat162_rn(z - hf.x, z_n - hf.y);
            ((unsigned*)g_x0gh)[idx >> 1] = *(unsigned*)&h2;
            ((unsigned*)g_x0gl)[idx >> 1] = *(unsigned*)&l2;
        }
    }
}

// ---------------- driver -----------------------------------------------------
extern "C" void kernel_launch(void* const* d_in, const int* in_sizes, int n_in,
                              void* d_out, int out_size) {
    const float* x0   = (const float*)d_in[0];
    const float* x1   = (const float*)d_in[1];
    const float* H    = (const float*)d_in[2];
    const float* Wn   = (const float*)d_in[3];
    const float* bn   = (const float*)d_in[4];
    const float* We   = (const float*)d_in[5];
    const float* be   = (const float*)d_in[6];
    const float* Wr   = (const float*)d_in[7];
    const float* br   = (const float*)d_in[8];
    const float* W1   = (const float*)d_in[9];
    const float* b1   = (const float*)d_in[10];
    const float* W2   = (const float*)d_in[11];
    const float* b2   = (const float*)d_in[12];
    const float* ln1g = (const float*)d_in[13];
    const float* ln1b = (const float*)d_in[14];
    const float* ln2g = (const float*)d_in[15];
    const float* ln2b = (const float*)d_in[16];
    const float* gl   = (const float*)d_in[17];
    const float* gr   = (const float*)d_in[18];

    float* out_x0 = (float*)d_out;
    float* out_x1 = (float*)d_out + (size_t)NN * DIM;

    float *p_x1a, *p_u, *p_x0g, *p_invse;
    __nv_bfloat162 *p_x0bf, *p_x1abf, *p_x0lbf;
    __nv_bfloat16 *p_wh, *p_wl;
    __nv_bfloat16 *p_tmpEh, *p_tmpEl, *p_msgh, *p_msgl, *p_reth, *p_retl;
    __nv_bfloat16 *p_x0gh, *p_x0gl, *p_hh, *p_hl;
    cudaGetSymbolAddress((void**)&p_x1a,  g_x1a);
    cudaGetSymbolAddress((void**)&p_u,    g_u);
    cudaGetSymbolAddress((void**)&p_x0g,  g_x0g);
    cudaGetSymbolAddress((void**)&p_invse, g_invse);
    cudaGetSymbolAddress((void**)&p_x0bf,  g_x0bf);
    cudaGetSymbolAddress((void**)&p_x1abf, g_x1abf);
    cudaGetSymbolAddress((void**)&p_x0lbf, g_x0lbf);
    cudaGetSymbolAddress((void**)&p_wh, g_wh);
    cudaGetSymbolAddress((void**)&p_wl, g_wl);
    cudaGetSymbolAddress((void**)&p_tmpEh, g_tmpEh);
    cudaGetSymbolAddress((void**)&p_tmpEl, g_tmpEl);
    cudaGetSymbolAddress((void**)&p_msgh, g_msgh);
    cudaGetSymbolAddress((void**)&p_msgl, g_msgl);
    cudaGetSymbolAddress((void**)&p_reth, g_reth);
    cudaGetSymbolAddress((void**)&p_retl, g_retl);
    cudaGetSymbolAddress((void**)&p_x0gh, g_x0gh);
    cudaGetSymbolAddress((void**)&p_x0gl, g_x0gl);
    cudaGetSymbolAddress((void**)&p_hh, g_hh);
    cudaGetSymbolAddress((void**)&p_hl, g_hl);

    // 1) sparse build + weight prepack (fused, DRAM-bound)
    build_csr_kernel<<<NN / 8, 256>>>(H, We, Wn, Wr, W1, W2);
    // 2) scatter + x0->bf16(*invsv)
    scatter_cvt_kernel<<<(NN * CAP_R) / 256, 256>>>(x0);
    // 3) tmpE = H_norm^T @ x0 -> hi/lo planes (publishes invse)
    spmm_edges_kernel<<<EE / 8, 256>>>((const uint2*)p_x0bf, p_tmpEh, p_tmpEl);
    // 4) x1a = x1 + tmpE @ We + be (fp32 + gather copy)   <-- ncu profiled slot
    gemm_tc_kernel<true, false><<<dim3(DIM / 128, EE / 64), 256>>>(
        p_tmpEh, p_tmpEl, p_wh + OFF_WE, p_wl + OFF_WE, be, x1, nullptr, p_x1a,
        nullptr, nullptr, p_x1abf, p_invse, EE, DIM, DIM);
    // 5) msg = H_norm @ x1a -> hi/lo planes
    spmm_nodes_kernel<<<NN / 8, 256>>>((const uint2*)p_x1abf, p_msgh, p_msgl);
    // 6) u = x0 + tanh(gl) * (msg @ Wn + bn)
    gemm_tc_kernel<true, false><<<dim3(DIM / 128, NN / 64), 256>>>(
        p_msgh, p_msgl, p_wh + OFF_WN, p_wl + OFF_WN, bn, x0, gl, p_u,
        nullptr, nullptr, nullptr, nullptr, NN, DIM, DIM);
    // 7) LN1 (gather copy) + LN2 (fp32 + hi/lo planes)
    ln_double_kernel<<<NN, DIM>>>(ln1g, ln1b, ln2g, ln2b);
    // 8) ret = H_norm^T @ x0_local -> hi/lo planes
    spmm_edges_kernel<<<EE / 8, 256>>>((const uint2*)p_x0lbf, p_reth, p_retl);
    // 9) x1_out = x1a + tanh(gr) * (ret @ Wr + br)
    gemm_tc_kernel<true, false><<<dim3(DIM / 128, EE / 64), 256>>>(
        p_reth, p_retl, p_wh + OFF_WR, p_wl + OFF_WR, br, p_x1a, gr, out_x1,
        nullptr, nullptr, nullptr, nullptr, EE, DIM, DIM);
    // 10) h = gelu(x0_global @ W1 + b1) -> hi/lo planes only
    gemm_tc_kernel<false, true><<<dim3((2 * DIM) / 128, NN / 64), 256>>>(
        p_x0gh, p_x0gl, p_wh + OFF_W1, p_wl + OFF_W1, b1, nullptr, nullptr, nullptr,
        (__nv_bfloat162*)p_hh, (__nv_bfloat162*)p_hl, nullptr, nullptr, NN, 2 * DIM, DIM);
    // 11) x0_out = x0_global + h @ W2 + b2
    gemm_tc_kernel<true, false><<<dim3(DIM / 128, NN / 64), 256>>>(
        p_hh, p_hl, p_wh + OFF_W2, p_wl + OFF_W2, b2, p_x0g, nullptr, out_x0,
        nullptr, nullptr, nullptr, nullptr, NN, DIM, 2 * DIM);

    (void)in_sizes; (void)n_in; (void)out_size;
}